// round 2
// baseline (speedup 1.0000x reference)
#include <cuda_runtime.h>
#include <math.h>

#define B_WIN   1024
#define NTOK    64
#define DIMC    512
#define NH      16
#define HD      32
#define M_TOT   (B_WIN * NTOK)           /* 65536 */
#define SCALE_F 0.17677669529663687f     /* 32^-0.5 */

/* ---- scratch (static device globals; no allocation) ---- */
__device__ float g_q[B_WIN * NH * NTOK * HD];      /* [b][h][n][d], pre-scaled */
__device__ float g_k[B_WIN * NH * NTOK * HD];
__device__ float g_v[B_WIN * NH * NTOK * HD];
__device__ float g_att[(size_t)M_TOT * DIMC];      /* [b][n][h*d] */
__device__ float g_bias[NH * NTOK * NTOK];         /* [h][i][j]   */

/* ================= bias table: A_phi + A_theta, head x 64 x 64 ============ */
__global__ void bias_kernel(const float* __restrict__ theta_max,
                            const float* __restrict__ a_p, const float* __restrict__ b_p,
                            const float* __restrict__ a_r, const float* __restrict__ b_r)
{
    int idx = blockIdx.x * 256 + threadIdx.x;   /* < 16*64*64 = 65536 */
    int h  = idx >> 12;
    int ij = idx & 4095;
    int i = ij >> 6, j = ij & 63;
    int ri = i >> 3, ci = i & 7;
    int rj = j >> 3, cj = j & 7;
    int dr = ri - rj;                /* radius  diff, [-7,7] */
    int dc = ci - cj;                /* azimuth diff, [-7,7] */
    int idx_r  = ((dr % 15) + 15) % 15;
    int idx_az = ((dc % 15) + 15) % 15;
    float az = (float)dc * (2.0f * 3.14159265358979323846f / 32.0f);
    float ra = (float)dr * (theta_max[0] / 32.0f);
    float bias = a_p[idx_az * NH + h] * cosf(az) + b_p[idx_az * NH + h] * sinf(az)
               + a_r[idx_r  * NH + h] * cosf(ra) + b_r[idx_r  * NH + h] * sinf(ra);
    g_bias[idx] = bias;
}

/* ================= SGEMM: C[M,N] = A[M,K] * W[N,K]^T + bias =============== */
/* 128x128 tile, BK=8, 256 threads, 8x8 per thread (4+4 split).              */
/* MODE 0: QKV (N=1536) -> scatter into g_q/g_k/g_v, SCALE on q.             */
/* MODE 1: proj (N=512) -> C = d_out; A taken from g_att.                    */
template<int MODE>
__global__ __launch_bounds__(256) void sgemm_kernel(
    const float* __restrict__ A, const float* __restrict__ W,
    const float* __restrict__ bias, float* __restrict__ C)
{
    __shared__ float As[8][128];
    __shared__ float Bs[8][128];

    const float* Abase = (MODE == 1) ? (const float*)g_att : A;

    const int tid  = threadIdx.x;
    const int m0   = blockIdx.y << 7;
    const int n0   = blockIdx.x << 7;
    const int lrow = tid >> 1;             /* 0..127 */
    const int lcol = (tid & 1) << 2;       /* 0 or 4 */
    const int ty   = tid >> 4;             /* 0..15 */
    const int tx   = tid & 15;             /* 0..15 */

    const float* Ap = Abase + (size_t)(m0 + lrow) * DIMC + lcol;
    const float* Wp = W     + (size_t)(n0 + lrow) * DIMC + lcol;

    float acc[8][8];
#pragma unroll
    for (int i = 0; i < 8; i++)
#pragma unroll
        for (int j = 0; j < 8; j++) acc[i][j] = 0.0f;

    for (int k0 = 0; k0 < DIMC; k0 += 8) {
        float4 av = *(const float4*)(Ap + k0);
        float4 wv = *(const float4*)(Wp + k0);
        __syncthreads();
        As[lcol + 0][lrow] = av.x; As[lcol + 1][lrow] = av.y;
        As[lcol + 2][lrow] = av.z; As[lcol + 3][lrow] = av.w;
        Bs[lcol + 0][lrow] = wv.x; Bs[lcol + 1][lrow] = wv.y;
        Bs[lcol + 2][lrow] = wv.z; Bs[lcol + 3][lrow] = wv.w;
        __syncthreads();
#pragma unroll
        for (int kk = 0; kk < 8; kk++) {
            float4 a0 = *(const float4*)&As[kk][ty << 2];
            float4 a1 = *(const float4*)&As[kk][64 + (ty << 2)];
            float4 b0 = *(const float4*)&Bs[kk][tx << 2];
            float4 b1 = *(const float4*)&Bs[kk][64 + (tx << 2)];
            float af[8] = {a0.x, a0.y, a0.z, a0.w, a1.x, a1.y, a1.z, a1.w};
            float bf[8] = {b0.x, b0.y, b0.z, b0.w, b1.x, b1.y, b1.z, b1.w};
#pragma unroll
            for (int i = 0; i < 8; i++)
#pragma unroll
                for (int j = 0; j < 8; j++) acc[i][j] += af[i] * bf[j];
        }
    }

#pragma unroll
    for (int ii = 0; ii < 8; ii++) {
        int m = m0 + ((ii < 4) ? ((ty << 2) + ii) : (64 + (ty << 2) + ii - 4));
#pragma unroll
        for (int half = 0; half < 2; half++) {
            int n = n0 + half * 64 + (tx << 2);
            float4 bv = *(const float4*)&bias[n];
            float4 r;
            r.x = acc[ii][half * 4 + 0] + bv.x;
            r.y = acc[ii][half * 4 + 1] + bv.y;
            r.z = acc[ii][half * 4 + 2] + bv.z;
            r.w = acc[ii][half * 4 + 3] + bv.w;
            if (MODE == 0) {
                int s = n >> 9;                 /* 0=q 1=k 2=v */
                if (s == 0) { r.x *= SCALE_F; r.y *= SCALE_F; r.z *= SCALE_F; r.w *= SCALE_F; }
                int h = (n >> 5) & 15, d = n & 31;
                int b = m >> 6, tok = m & 63;
                float* dst = (s == 0) ? g_q : ((s == 1) ? g_k : g_v);
                *(float4*)&dst[(((size_t)(b * NH + h)) * NTOK + tok) * HD + d] = r;
            } else {
                *(float4*)&C[(size_t)m * DIMC + n] = r;
            }
        }
    }
}

/* ================= fused attention per (b,h): S=qk^T+bias, softmax, Pv ==== */
__global__ __launch_bounds__(256) void attn_kernel()
{
    const int bh = blockIdx.x;            /* 0 .. 16383 */
    const int b = bh >> 4, h = bh & 15;

    __shared__ float qT[32][68];          /* [d][n], stride 68 for f4 align   */
    __shared__ float kT[32][68];
    __shared__ float vsm[64][32];         /* [n][d] natural                   */
    __shared__ float Ss[64][65];          /* [i][j], stride 65 (bank spread)  */

    const float* qg = g_q + (size_t)bh * (NTOK * HD);
    const float* kg = g_k + (size_t)bh * (NTOK * HD);
    const float* vg = g_v + (size_t)bh * (NTOK * HD);

    const int tid = threadIdx.x;
    for (int e = tid; e < NTOK * HD; e += 256) {
        int n = e >> 5, d = e & 31;
        qT[d][n] = qg[e];
        kT[d][n] = kg[e];
        ((float*)vsm)[e] = vg[e];
    }
    __syncthreads();

    /* ---- S = qT^T kT  (each thread: 4x4 tile) + bias ---- */
    const int ty = tid >> 4, tx = tid & 15;
    const int i0 = ty << 2, j0 = tx << 2;
    float s4[4][4];
#pragma unroll
    for (int i = 0; i < 4; i++)
#pragma unroll
        for (int j = 0; j < 4; j++) s4[i][j] = 0.0f;
#pragma unroll
    for (int kk = 0; kk < 32; kk++) {
        float4 qa = *(const float4*)&qT[kk][i0];
        float4 kb = *(const float4*)&kT[kk][j0];
        float af[4] = {qa.x, qa.y, qa.z, qa.w};
        float bf[4] = {kb.x, kb.y, kb.z, kb.w};
#pragma unroll
        for (int i = 0; i < 4; i++)
#pragma unroll
            for (int j = 0; j < 4; j++) s4[i][j] += af[i] * bf[j];
    }
    const float* bp = g_bias + (h << 12);
#pragma unroll
    for (int i = 0; i < 4; i++) {
        float4 bv = *(const float4*)&bp[(i0 + i) * 64 + j0];
        Ss[i0 + i][j0 + 0] = s4[i][0] + bv.x;
        Ss[i0 + i][j0 + 1] = s4[i][1] + bv.y;
        Ss[i0 + i][j0 + 2] = s4[i][2] + bv.z;
        Ss[i0 + i][j0 + 3] = s4[i][3] + bv.w;
    }
    __syncthreads();

    /* ---- softmax over j: 4 threads per row, shfl-combined ---- */
    const int r   = tid >> 2;             /* row 0..63 */
    const int seg = tid & 3;              /* 16-col segment */
    float* row = &Ss[0][0] + r * 65;
    float mx = -1e30f;
#pragma unroll
    for (int j = 0; j < 16; j++) mx = fmaxf(mx, row[seg * 16 + j]);
    mx = fmaxf(mx, __shfl_xor_sync(0xffffffffu, mx, 1));
    mx = fmaxf(mx, __shfl_xor_sync(0xffffffffu, mx, 2));
    float ev[16];
    float sum = 0.0f;
#pragma unroll
    for (int j = 0; j < 16; j++) { ev[j] = __expf(row[seg * 16 + j] - mx); sum += ev[j]; }
    sum += __shfl_xor_sync(0xffffffffu, sum, 1);
    sum += __shfl_xor_sync(0xffffffffu, sum, 2);
    float inv = 1.0f / sum;
#pragma unroll
    for (int j = 0; j < 16; j++) row[seg * 16 + j] = ev[j] * inv;
    __syncthreads();

    /* ---- O = P @ v : thread (r, dseg) computes O[r][dseg*8 .. +7] ---- */
    const int d0 = seg << 3;
    float oa[8];
#pragma unroll
    for (int i = 0; i < 8; i++) oa[i] = 0.0f;
#pragma unroll 8
    for (int j = 0; j < 64; j++) {
        float p = Ss[r][j];
        float4 v0 = *(const float4*)&vsm[j][d0];
        float4 v1 = *(const float4*)&vsm[j][d0 + 4];
        oa[0] += p * v0.x; oa[1] += p * v0.y; oa[2] += p * v0.z; oa[3] += p * v0.w;
        oa[4] += p * v1.x; oa[5] += p * v1.y; oa[6] += p * v1.z; oa[7] += p * v1.w;
    }
    float* og = g_att + (size_t)(b * NTOK + r) * DIMC + h * HD + d0;
    *(float4*)(og)     = make_float4(oa[0], oa[1], oa[2], oa[3]);
    *(float4*)(og + 4) = make_float4(oa[4], oa[5], oa[6], oa[7]);
}

/* ========================================================================= */
extern "C" void kernel_launch(void* const* d_in, const int* in_sizes, int n_in,
                              void* d_out, int out_size)
{
    (void)in_sizes; (void)n_in; (void)out_size;
    const float* x      = (const float*)d_in[0];
    const float* theta  = (const float*)d_in[1];
    const float* qkv_w  = (const float*)d_in[2];
    const float* qkv_b  = (const float*)d_in[3];
    const float* proj_w = (const float*)d_in[4];
    const float* proj_b = (const float*)d_in[5];
    const float* a_p    = (const float*)d_in[6];
    const float* b_p    = (const float*)d_in[7];
    const float* a_r    = (const float*)d_in[8];
    const float* b_r    = (const float*)d_in[9];
    float* out = (float*)d_out;

    bias_kernel<<<256, 256>>>(theta, a_p, b_p, a_r, b_r);
    sgemm_kernel<0><<<dim3(1536 / 128, M_TOT / 128), 256>>>(x, qkv_w, qkv_b, nullptr);
    attn_kernel<<<B_WIN * NH, 256>>>();
    sgemm_kernel<1><<<dim3(DIMC / 128, M_TOT / 128), 256>>>(nullptr, proj_w, proj_b, out);
}

// round 4
// speedup vs baseline: 1.9135x; 1.9135x over previous
#include <cuda_runtime.h>
#include <cuda_bf16.h>
#include <stdint.h>
#include <math.h>

#define B_WIN   1024
#define NTOK    64
#define DIMC    512
#define NH      16
#define HD      32
#define M_TOT   (B_WIN * NTOK)           /* 65536 */
#define SCALE_F 0.17677669529663687f     /* 32^-0.5 */

/* ---------------- static device scratch (no allocation) ------------------ */
__device__ float g_q[M_TOT * DIMC];                /* [b][h][n][d], scaled  */
__device__ float g_k[M_TOT * DIMC];
__device__ float g_v[M_TOT * DIMC];
__device__ float g_bias[NH * NTOK * NTOK];
__device__ __nv_bfloat16 g_xhi[(size_t)M_TOT * DIMC];
__device__ __nv_bfloat16 g_xlo[(size_t)M_TOT * DIMC];
__device__ __nv_bfloat16 g_atthi[(size_t)M_TOT * DIMC];   /* [b*64+tok][h*32+d] */
__device__ __nv_bfloat16 g_attlo[(size_t)M_TOT * DIMC];
__device__ __nv_bfloat16 g_wqhi[3 * DIMC * DIMC];
__device__ __nv_bfloat16 g_wqlo[3 * DIMC * DIMC];
__device__ __nv_bfloat16 g_wphi[DIMC * DIMC];
__device__ __nv_bfloat16 g_wplo[DIMC * DIMC];

/* ---------------- portable tensor-core helpers (sm_80+) ------------------ */
__device__ __forceinline__ uint32_t smem_u32(const void* p) {
    return (uint32_t)__cvta_generic_to_shared(p);
}
__device__ __forceinline__ void ldsm4(uint32_t* r, uint32_t addr) {
    asm volatile("ldmatrix.sync.aligned.m8n8.x4.shared.b16 {%0,%1,%2,%3}, [%4];"
        : "=r"(r[0]), "=r"(r[1]), "=r"(r[2]), "=r"(r[3]) : "r"(addr));
}
__device__ __forceinline__ void mma_bf16(float* d, const uint32_t* a, const uint32_t* b) {
    asm volatile("mma.sync.aligned.m16n8k16.row.col.f32.bf16.bf16.f32 "
        "{%0,%1,%2,%3}, {%4,%5,%6,%7}, {%8,%9}, {%0,%1,%2,%3};"
        : "+f"(d[0]), "+f"(d[1]), "+f"(d[2]), "+f"(d[3])
        : "r"(a[0]), "r"(a[1]), "r"(a[2]), "r"(a[3]), "r"(b[0]), "r"(b[1]));
}
#define CP_ASYNC16(dst, src) \
    asm volatile("cp.async.cg.shared.global [%0], [%1], 16;" :: "r"(dst), "l"(src))
#define CP_COMMIT()  asm volatile("cp.async.commit_group;" ::: "memory")
#define CP_WAIT1()   asm volatile("cp.async.wait_group 1;" ::: "memory")
#define CP_WAIT0()   asm volatile("cp.async.wait_group 0;" ::: "memory")

/* ================= bias table ============================================ */
__global__ void bias_kernel(const float* __restrict__ theta_max,
                            const float* __restrict__ a_p, const float* __restrict__ b_p,
                            const float* __restrict__ a_r, const float* __restrict__ b_r)
{
    int idx = blockIdx.x * 256 + threadIdx.x;
    int h = idx >> 12;
    int ij = idx & 4095;
    int i = ij >> 6, j = ij & 63;
    int dr = (i >> 3) - (j >> 3);
    int dc = (i & 7) - (j & 7);
    int idx_r  = ((dr % 15) + 15) % 15;
    int idx_az = ((dc % 15) + 15) % 15;
    float az = (float)dc * (2.0f * 3.14159265358979323846f / 32.0f);
    float ra = (float)dr * (theta_max[0] / 32.0f);
    g_bias[idx] = a_p[idx_az * NH + h] * cosf(az) + b_p[idx_az * NH + h] * sinf(az)
                + a_r[idx_r  * NH + h] * cosf(ra) + b_r[idx_r  * NH + h] * sinf(ra);
}

/* ================= fp32 -> bf16 hi/lo split ============================== */
__device__ __forceinline__ void split1(float x, unsigned short& h, unsigned short& l) {
    __nv_bfloat16 hb = __float2bfloat16(x);
    float res = x - __bfloat162float(hb);
    h = __bfloat16_as_ushort(hb);
    l = __bfloat16_as_ushort(__float2bfloat16(res));
}
__global__ void split_kernel(const float* __restrict__ src, int which, int n4)
{
    int i = blockIdx.x * 256 + threadIdx.x;
    if (i >= n4) return;
    float4 v = ((const float4*)src)[i];
    unsigned short h0, h1, h2, h3, l0, l1, l2, l3;
    split1(v.x, h0, l0); split1(v.y, h1, l1);
    split1(v.z, h2, l2); split1(v.w, h3, l3);
    uint2 H = make_uint2((uint32_t)h0 | ((uint32_t)h1 << 16),
                         (uint32_t)h2 | ((uint32_t)h3 << 16));
    uint2 L = make_uint2((uint32_t)l0 | ((uint32_t)l1 << 16),
                         (uint32_t)l2 | ((uint32_t)l3 << 16));
    __nv_bfloat16 *hp, *lp;
    if (which == 0)      { hp = g_xhi; lp = g_xlo; }
    else if (which == 1) { hp = g_wqhi; lp = g_wqlo; }
    else                 { hp = g_wphi; lp = g_wplo; }
    ((uint2*)hp)[i] = H;
    ((uint2*)lp)[i] = L;
}

/* ================= mma.sync split-bf16 GEMM ============================== */
/* C[M,N] = A[M,512] * W[N,512]^T + bias.  CTA tile 128x128, 8 warps.       */
/* smem stage (32KB): Ahi | Alo | Whi | Wlo, each 128 rows x 32 bf16,       */
/* stored as 16B chunks with XOR swizzle: off16(r,half,ksl) =               */
/*     ksl*256 + r*2 + (half ^ ((r>>2)&1)).                                 */
/* MODE 0: A=g_x*, W=g_wq* (N=1536) -> scatter q/k/v (+SCALE on q).         */
/* MODE 1: A=g_att*, W=g_wp* (N=512) -> out.                                */
#define STAGE_B 32768
#define SMEM_TOTAL (2 * STAGE_B)

template<int MODE>
__global__ __launch_bounds__(256, 2) void mma_gemm(const float* __restrict__ bias,
                                                   float* __restrict__ out)
{
    extern __shared__ char smem[];
    const uint32_t sb = smem_u32(smem);
    const int tid = threadIdx.x, wid = tid >> 5, lane = tid & 31;
    const int m0 = blockIdx.y << 7;
    const int n0 = blockIdx.x << 7;
    const int wm = (wid & 3) << 5;          /* warp row offset (0..96)  */
    const int wn = (wid >> 2) << 6;         /* warp col offset (0/64)   */

    const __nv_bfloat16* __restrict__ Ahi = (MODE == 0) ? g_xhi : g_atthi;
    const __nv_bfloat16* __restrict__ Alo = (MODE == 0) ? g_xlo : g_attlo;
    const __nv_bfloat16* __restrict__ Whi = (MODE == 0) ? g_wqhi : g_wphi;
    const __nv_bfloat16* __restrict__ Wlo = (MODE == 0) ? g_wqlo : g_wplo;

    float acc[2][8][4];
#pragma unroll
    for (int a = 0; a < 2; a++)
#pragma unroll
        for (int b = 0; b < 8; b++)
#pragma unroll
            for (int c = 0; c < 4; c++) acc[a][b][c] = 0.0f;

    /* loader decomposition: chunk id c in [0,512): r=c>>2, q=c&3 */
    const int c_r0   = tid >> 2,          c_q0 = tid & 3;
    const int c_r1   = (tid + 256) >> 2,  c_q1 = tid & 3;      /* q same */
    const int ksl0 = c_q0 >> 1, half0 = c_q0 & 1;
    const uint32_t off0 = 16u * (ksl0 * 256 + c_r0 * 2 + (half0 ^ ((c_r0 >> 2) & 1)));
    const uint32_t off1 = 16u * (ksl0 * 256 + c_r1 * 2 + (half0 ^ ((c_r1 >> 2) & 1)));
    const int kc0 = ksl0 * 16 + half0 * 8;

#define ISSUE(ch) do {                                                         \
    const uint32_t stg = sb + ((ch) & 1) * STAGE_B;                            \
    const int kk = ((ch) << 5) + kc0;                                          \
    size_t a0 = (size_t)(m0 + c_r0) * DIMC + kk;                               \
    size_t a1 = (size_t)(m0 + c_r1) * DIMC + kk;                               \
    size_t b0 = (size_t)(n0 + c_r0) * DIMC + kk;                               \
    size_t b1 = (size_t)(n0 + c_r1) * DIMC + kk;                               \
    CP_ASYNC16(stg + off0,         Ahi + a0);                                  \
    CP_ASYNC16(stg + off1,         Ahi + a1);                                  \
    CP_ASYNC16(stg + 8192  + off0, Alo + a0);                                  \
    CP_ASYNC16(stg + 8192  + off1, Alo + a1);                                  \
    CP_ASYNC16(stg + 16384 + off0, Whi + b0);                                  \
    CP_ASYNC16(stg + 16384 + off1, Whi + b1);                                  \
    CP_ASYNC16(stg + 24576 + off0, Wlo + b0);                                  \
    CP_ASYNC16(stg + 24576 + off1, Wlo + b1);                                  \
    CP_COMMIT();                                                               \
} while (0)

    ISSUE(0);
    const int rloc = lane & 15, hsel = lane >> 4;
    for (int ch = 0; ch < 16; ++ch) {
        if (ch < 15) { ISSUE(ch + 1); CP_WAIT1(); }
        else         { CP_WAIT0(); }
        __syncthreads();
        const uint32_t stg = sb + (ch & 1) * STAGE_B;
#pragma unroll
        for (int ks = 0; ks < 2; ++ks) {
            uint32_t ah[2][4], al[2][4];
#pragma unroll
            for (int mt = 0; mt < 2; ++mt) {
                int r = wm + mt * 16 + rloc;
                uint32_t off = 16u * (ks * 256 + r * 2 + (hsel ^ ((r >> 2) & 1)));
                ldsm4(ah[mt], stg + off);
                ldsm4(al[mt], stg + 8192 + off);
            }
#pragma unroll
            for (int g = 0; g < 4; ++g) {
                int r = wn + g * 16 + rloc;
                uint32_t off = 16u * (ks * 256 + r * 2 + (hsel ^ ((r >> 2) & 1)));
                uint32_t bh[4], bl[4];
                ldsm4(bh, stg + 16384 + off);
                ldsm4(bl, stg + 24576 + off);
                uint32_t b0h[2] = {bh[0], bh[2]}, b1h[2] = {bh[1], bh[3]};
                uint32_t b0l[2] = {bl[0], bl[2]}, b1l[2] = {bl[1], bl[3]};
#pragma unroll
                for (int mt = 0; mt < 2; ++mt) {
                    mma_bf16(acc[mt][2 * g],     ah[mt], b0h);
                    mma_bf16(acc[mt][2 * g + 1], ah[mt], b1h);
                    mma_bf16(acc[mt][2 * g],     ah[mt], b0l);
                    mma_bf16(acc[mt][2 * g + 1], ah[mt], b1l);
                    mma_bf16(acc[mt][2 * g],     al[mt], b0h);
                    mma_bf16(acc[mt][2 * g + 1], al[mt], b1h);
                }
            }
        }
        __syncthreads();
    }
#undef ISSUE

    /* ---- epilogue: frag (mt, f) rows m..m+8, cols n..n+1 ---- */
#pragma unroll
    for (int mt = 0; mt < 2; ++mt) {
#pragma unroll
        for (int f = 0; f < 8; ++f) {
            const int n = n0 + wn + (f >> 1) * 16 + (f & 1) * 8 + (lane & 3) * 2;
            const float2 bv = *(const float2*)&bias[n];
#pragma unroll
            for (int hrow = 0; hrow < 2; ++hrow) {
                const int m = m0 + wm + mt * 16 + (lane >> 2) + hrow * 8;
                float vx = acc[mt][f][hrow * 2 + 0] + bv.x;
                float vy = acc[mt][f][hrow * 2 + 1] + bv.y;
                if (MODE == 0) {
                    const int sel = n >> 9;
                    const int h = (n >> 5) & 15, d = n & 31;
                    if (sel == 0) { vx *= SCALE_F; vy *= SCALE_F; }
                    float* dst = (sel == 0) ? g_q : ((sel == 1) ? g_k : g_v);
                    *(float2*)&dst[(((size_t)(m >> 6) * NH + h) * NTOK + (m & 63)) * HD + d]
                        = make_float2(vx, vy);
                } else {
                    *(float2*)&out[(size_t)m * DIMC + n] = make_float2(vx, vy);
                }
            }
        }
    }
}

/* ================= fused attention per (b,h) ============================= */
__global__ __launch_bounds__(256) void attn_kernel()
{
    const int bh = blockIdx.x;
    const int b = bh >> 4, h = bh & 15;

    __shared__ float qT[32][68];
    __shared__ float kT[32][68];
    __shared__ float vsm[64][32];
    __shared__ float Ss[64][65];

    const float* qg = g_q + (size_t)bh * (NTOK * HD);
    const float* kg = g_k + (size_t)bh * (NTOK * HD);
    const float* vg = g_v + (size_t)bh * (NTOK * HD);

    const int tid = threadIdx.x;
    for (int e = tid; e < NTOK * HD; e += 256) {
        int n = e >> 5, d = e & 31;
        qT[d][n] = qg[e];
        kT[d][n] = kg[e];
        ((float*)vsm)[e] = vg[e];
    }
    __syncthreads();

    const int ty = tid >> 4, tx = tid & 15;
    const int i0 = ty << 2, j0 = tx << 2;
    float s4[4][4];
#pragma unroll
    for (int i = 0; i < 4; i++)
#pragma unroll
        for (int j = 0; j < 4; j++) s4[i][j] = 0.0f;
#pragma unroll
    for (int kk = 0; kk < 32; kk++) {
        float4 qa = *(const float4*)&qT[kk][i0];
        float4 kb = *(const float4*)&kT[kk][j0];
        float af[4] = {qa.x, qa.y, qa.z, qa.w};
        float bf[4] = {kb.x, kb.y, kb.z, kb.w};
#pragma unroll
        for (int i = 0; i < 4; i++)
#pragma unroll
            for (int j = 0; j < 4; j++) s4[i][j] += af[i] * bf[j];
    }
    const float* bp = g_bias + (h << 12);
#pragma unroll
    for (int i = 0; i < 4; i++) {
        float4 bv = *(const float4*)&bp[(i0 + i) * 64 + j0];
        Ss[i0 + i][j0 + 0] = s4[i][0] + bv.x;
        Ss[i0 + i][j0 + 1] = s4[i][1] + bv.y;
        Ss[i0 + i][j0 + 2] = s4[i][2] + bv.z;
        Ss[i0 + i][j0 + 3] = s4[i][3] + bv.w;
    }
    __syncthreads();

    const int r   = tid >> 2;
    const int seg = tid & 3;
    float* row = &Ss[0][0] + r * 65;
    float mx = -1e30f;
#pragma unroll
    for (int j = 0; j < 16; j++) mx = fmaxf(mx, row[seg * 16 + j]);
    mx = fmaxf(mx, __shfl_xor_sync(0xffffffffu, mx, 1));
    mx = fmaxf(mx, __shfl_xor_sync(0xffffffffu, mx, 2));
    float ev[16];
    float sum = 0.0f;
#pragma unroll
    for (int j = 0; j < 16; j++) { ev[j] = __expf(row[seg * 16 + j] - mx); sum += ev[j]; }
    sum += __shfl_xor_sync(0xffffffffu, sum, 1);
    sum += __shfl_xor_sync(0xffffffffu, sum, 2);
    float inv = 1.0f / sum;
#pragma unroll
    for (int j = 0; j < 16; j++) row[seg * 16 + j] = ev[j] * inv;
    __syncthreads();

    const int d0 = seg << 3;
    float oa[8];
#pragma unroll
    for (int i = 0; i < 8; i++) oa[i] = 0.0f;
#pragma unroll 8
    for (int j = 0; j < 64; j++) {
        float p = Ss[r][j];
        float4 v0 = *(const float4*)&vsm[j][d0];
        float4 v1 = *(const float4*)&vsm[j][d0 + 4];
        oa[0] += p * v0.x; oa[1] += p * v0.y; oa[2] += p * v0.z; oa[3] += p * v0.w;
        oa[4] += p * v1.x; oa[5] += p * v1.y; oa[6] += p * v1.z; oa[7] += p * v1.w;
    }
    /* write split bf16 directly for the proj GEMM */
    unsigned short hs[8], ls[8];
#pragma unroll
    for (int i = 0; i < 8; i++) split1(oa[i], hs[i], ls[i]);
    uint4 H = make_uint4((uint32_t)hs[0] | ((uint32_t)hs[1] << 16),
                         (uint32_t)hs[2] | ((uint32_t)hs[3] << 16),
                         (uint32_t)hs[4] | ((uint32_t)hs[5] << 16),
                         (uint32_t)hs[6] | ((uint32_t)hs[7] << 16));
    uint4 L = make_uint4((uint32_t)ls[0] | ((uint32_t)ls[1] << 16),
                         (uint32_t)ls[2] | ((uint32_t)ls[3] << 16),
                         (uint32_t)ls[4] | ((uint32_t)ls[5] << 16),
                         (uint32_t)ls[6] | ((uint32_t)ls[7] << 16));
    size_t ob = (size_t)(b * NTOK + r) * DIMC + h * HD + d0;
    *(uint4*)&g_atthi[ob] = H;
    *(uint4*)&g_attlo[ob] = L;
}

/* ========================================================================= */
extern "C" void kernel_launch(void* const* d_in, const int* in_sizes, int n_in,
                              void* d_out, int out_size)
{
    (void)in_sizes; (void)n_in; (void)out_size;
    const float* x      = (const float*)d_in[0];
    const float* theta  = (const float*)d_in[1];
    const float* qkv_w  = (const float*)d_in[2];
    const float* qkv_b  = (const float*)d_in[3];
    const float* proj_w = (const float*)d_in[4];
    const float* proj_b = (const float*)d_in[5];
    const float* a_p    = (const float*)d_in[6];
    const float* b_p    = (const float*)d_in[7];
    const float* a_r    = (const float*)d_in[8];
    const float* b_r    = (const float*)d_in[9];
    float* out = (float*)d_out;

    static int smem_set = 0;
    if (!smem_set) {
        cudaFuncSetAttribute(mma_gemm<0>, cudaFuncAttributeMaxDynamicSharedMemorySize, SMEM_TOTAL);
        cudaFuncSetAttribute(mma_gemm<1>, cudaFuncAttributeMaxDynamicSharedMemorySize, SMEM_TOTAL);
        smem_set = 1;
    }

    bias_kernel<<<256, 256>>>(theta, a_p, b_p, a_r, b_r);
    split_kernel<<<(M_TOT * DIMC / 4 + 255) / 256, 256>>>(x, 0, M_TOT * DIMC / 4);
    split_kernel<<<(3 * DIMC * DIMC / 4 + 255) / 256, 256>>>(qkv_w, 1, 3 * DIMC * DIMC / 4);
    split_kernel<<<(DIMC * DIMC / 4 + 255) / 256, 256>>>(proj_w, 2, DIMC * DIMC / 4);
    mma_gemm<0><<<dim3(12, 512), 256, SMEM_TOTAL>>>(qkv_b, nullptr);
    attn_kernel<<<B_WIN * NH, 256>>>();
    mma_gemm<1><<<dim3(4, 512), 256, SMEM_TOTAL>>>(proj_b, out);
}

// round 5
// speedup vs baseline: 1.9164x; 1.0015x over previous
#include <cuda_runtime.h>
#include <cuda_bf16.h>
#include <stdint.h>
#include <math.h>

#define B_WIN   1024
#define NTOK    64
#define DIMC    512
#define NH      16
#define HD      32
#define M_TOT   (B_WIN * NTOK)           /* 65536 */
#define SCALE_F 0.17677669529663687f     /* 32^-0.5 */

/* ---------------- static device scratch (no allocation) ------------------ */
__device__ float g_q[M_TOT * DIMC];                /* [b][h][n][d], scaled  */
__device__ float g_k[M_TOT * DIMC];
__device__ float g_v[M_TOT * DIMC];
__device__ float g_bias[NH * NTOK * NTOK];
__device__ __nv_bfloat16 g_xhi[(size_t)M_TOT * DIMC];
__device__ __nv_bfloat16 g_xlo[(size_t)M_TOT * DIMC];
__device__ __nv_bfloat16 g_atthi[(size_t)M_TOT * DIMC];   /* [b*64+tok][h*32+d] */
__device__ __nv_bfloat16 g_attlo[(size_t)M_TOT * DIMC];
__device__ __nv_bfloat16 g_wqhi[3 * DIMC * DIMC];
__device__ __nv_bfloat16 g_wqlo[3 * DIMC * DIMC];
__device__ __nv_bfloat16 g_wphi[DIMC * DIMC];
__device__ __nv_bfloat16 g_wplo[DIMC * DIMC];

/* ---------------- portable tensor-core helpers (sm_80+) ------------------ */
__device__ __forceinline__ uint32_t smem_u32(const void* p) {
    return (uint32_t)__cvta_generic_to_shared(p);
}
__device__ __forceinline__ void ldsm4(uint32_t* r, uint32_t addr) {
    asm volatile("ldmatrix.sync.aligned.m8n8.x4.shared.b16 {%0,%1,%2,%3}, [%4];"
        : "=r"(r[0]), "=r"(r[1]), "=r"(r[2]), "=r"(r[3]) : "r"(addr));
}
__device__ __forceinline__ void mma_bf16(float* d, const uint32_t* a, const uint32_t* b) {
    asm volatile("mma.sync.aligned.m16n8k16.row.col.f32.bf16.bf16.f32 "
        "{%0,%1,%2,%3}, {%4,%5,%6,%7}, {%8,%9}, {%0,%1,%2,%3};"
        : "+f"(d[0]), "+f"(d[1]), "+f"(d[2]), "+f"(d[3])
        : "r"(a[0]), "r"(a[1]), "r"(a[2]), "r"(a[3]), "r"(b[0]), "r"(b[1]));
}
#define CP_ASYNC16(dst, src) \
    asm volatile("cp.async.cg.shared.global [%0], [%1], 16;" :: "r"(dst), "l"(src))
#define CP_COMMIT()  asm volatile("cp.async.commit_group;" ::: "memory")
#define CP_WAIT1()   asm volatile("cp.async.wait_group 1;" ::: "memory")
#define CP_WAIT0()   asm volatile("cp.async.wait_group 0;" ::: "memory")

/* ================= bias table ============================================ */
__global__ void bias_kernel(const float* __restrict__ theta_max,
                            const float* __restrict__ a_p, const float* __restrict__ b_p,
                            const float* __restrict__ a_r, const float* __restrict__ b_r)
{
    int idx = blockIdx.x * 256 + threadIdx.x;
    int h = idx >> 12;
    int ij = idx & 4095;
    int i = ij >> 6, j = ij & 63;
    int dr = (i >> 3) - (j >> 3);
    int dc = (i & 7) - (j & 7);
    int idx_r  = ((dr % 15) + 15) % 15;
    int idx_az = ((dc % 15) + 15) % 15;
    float az = (float)dc * (2.0f * 3.14159265358979323846f / 32.0f);
    float ra = (float)dr * (theta_max[0] / 32.0f);
    g_bias[idx] = a_p[idx_az * NH + h] * cosf(az) + b_p[idx_az * NH + h] * sinf(az)
                + a_r[idx_r  * NH + h] * cosf(ra) + b_r[idx_r  * NH + h] * sinf(ra);
}

/* ================= fp32 -> bf16 hi/lo split ============================== */
__device__ __forceinline__ void split1(float x, unsigned short& h, unsigned short& l) {
    __nv_bfloat16 hb = __float2bfloat16(x);
    float res = x - __bfloat162float(hb);
    h = __bfloat16_as_ushort(hb);
    l = __bfloat16_as_ushort(__float2bfloat16(res));
}
__global__ void split_kernel(const float* __restrict__ src, int which, int n4)
{
    int i = blockIdx.x * 256 + threadIdx.x;
    if (i >= n4) return;
    float4 v = ((const float4*)src)[i];
    unsigned short h0, h1, h2, h3, l0, l1, l2, l3;
    split1(v.x, h0, l0); split1(v.y, h1, l1);
    split1(v.z, h2, l2); split1(v.w, h3, l3);
    uint2 H = make_uint2((uint32_t)h0 | ((uint32_t)h1 << 16),
                         (uint32_t)h2 | ((uint32_t)h3 << 16));
    uint2 L = make_uint2((uint32_t)l0 | ((uint32_t)l1 << 16),
                         (uint32_t)l2 | ((uint32_t)l3 << 16));
    __nv_bfloat16 *hp, *lp;
    if (which == 0)      { hp = g_xhi; lp = g_xlo; }
    else if (which == 1) { hp = g_wqhi; lp = g_wqlo; }
    else                 { hp = g_wphi; lp = g_wplo; }
    ((uint2*)hp)[i] = H;
    ((uint2*)lp)[i] = L;
}

/* ================= mma.sync split-bf16 GEMM ============================== */
/* C[M,N] = A[M,512] * W[N,512]^T + bias.  CTA tile 128x128, 8 warps.       */
/* smem stage (32KB): Ahi | Alo | Whi | Wlo, each 128 rows x 32 bf16,       */
/* stored as 16B chunks with XOR swizzle: off16(r,half,ksl) =               */
/*     ksl*256 + r*2 + (half ^ ((r>>2)&1)).                                 */
/* MODE 0: A=g_x*, W=g_wq* (N=1536) -> scatter q/k/v (+SCALE on q).         */
/* MODE 1: A=g_att*, W=g_wp* (N=512) -> out.                                */
#define STAGE_B 32768
#define SMEM_TOTAL (2 * STAGE_B)

template<int MODE>
__global__ __launch_bounds__(256, 2) void mma_gemm(const float* __restrict__ bias,
                                                   float* __restrict__ out)
{
    extern __shared__ char smem[];
    const uint32_t sb = smem_u32(smem);
    const int tid = threadIdx.x, wid = tid >> 5, lane = tid & 31;
    const int m0 = blockIdx.y << 7;
    const int n0 = blockIdx.x << 7;
    const int wm = (wid & 3) << 5;          /* warp row offset (0..96)  */
    const int wn = (wid >> 2) << 6;         /* warp col offset (0/64)   */

    const __nv_bfloat16* __restrict__ Ahi = (MODE == 0) ? g_xhi : g_atthi;
    const __nv_bfloat16* __restrict__ Alo = (MODE == 0) ? g_xlo : g_attlo;
    const __nv_bfloat16* __restrict__ Whi = (MODE == 0) ? g_wqhi : g_wphi;
    const __nv_bfloat16* __restrict__ Wlo = (MODE == 0) ? g_wqlo : g_wplo;

    float acc[2][8][4];
#pragma unroll
    for (int a = 0; a < 2; a++)
#pragma unroll
        for (int b = 0; b < 8; b++)
#pragma unroll
            for (int c = 0; c < 4; c++) acc[a][b][c] = 0.0f;

    /* loader decomposition: chunk id c in [0,512): r=c>>2, q=c&3 */
    const int c_r0   = tid >> 2,          c_q0 = tid & 3;
    const int c_r1   = (tid + 256) >> 2,  c_q1 = tid & 3;      /* q same */
    const int ksl0 = c_q0 >> 1, half0 = c_q0 & 1;
    const uint32_t off0 = 16u * (ksl0 * 256 + c_r0 * 2 + (half0 ^ ((c_r0 >> 2) & 1)));
    const uint32_t off1 = 16u * (ksl0 * 256 + c_r1 * 2 + (half0 ^ ((c_r1 >> 2) & 1)));
    const int kc0 = ksl0 * 16 + half0 * 8;

#define ISSUE(ch) do {                                                         \
    const uint32_t stg = sb + ((ch) & 1) * STAGE_B;                            \
    const int kk = ((ch) << 5) + kc0;                                          \
    size_t a0 = (size_t)(m0 + c_r0) * DIMC + kk;                               \
    size_t a1 = (size_t)(m0 + c_r1) * DIMC + kk;                               \
    size_t b0 = (size_t)(n0 + c_r0) * DIMC + kk;                               \
    size_t b1 = (size_t)(n0 + c_r1) * DIMC + kk;                               \
    CP_ASYNC16(stg + off0,         Ahi + a0);                                  \
    CP_ASYNC16(stg + off1,         Ahi + a1);                                  \
    CP_ASYNC16(stg + 8192  + off0, Alo + a0);                                  \
    CP_ASYNC16(stg + 8192  + off1, Alo + a1);                                  \
    CP_ASYNC16(stg + 16384 + off0, Whi + b0);                                  \
    CP_ASYNC16(stg + 16384 + off1, Whi + b1);                                  \
    CP_ASYNC16(stg + 24576 + off0, Wlo + b0);                                  \
    CP_ASYNC16(stg + 24576 + off1, Wlo + b1);                                  \
    CP_COMMIT();                                                               \
} while (0)

    ISSUE(0);
    const int rloc = lane & 15, hsel = lane >> 4;
    for (int ch = 0; ch < 16; ++ch) {
        if (ch < 15) { ISSUE(ch + 1); CP_WAIT1(); }
        else         { CP_WAIT0(); }
        __syncthreads();
        const uint32_t stg = sb + (ch & 1) * STAGE_B;
#pragma unroll
        for (int ks = 0; ks < 2; ++ks) {
            uint32_t ah[2][4], al[2][4];
#pragma unroll
            for (int mt = 0; mt < 2; ++mt) {
                int r = wm + mt * 16 + rloc;
                uint32_t off = 16u * (ks * 256 + r * 2 + (hsel ^ ((r >> 2) & 1)));
                ldsm4(ah[mt], stg + off);
                ldsm4(al[mt], stg + 8192 + off);
            }
#pragma unroll
            for (int g = 0; g < 4; ++g) {
                int r = wn + g * 16 + rloc;
                uint32_t off = 16u * (ks * 256 + r * 2 + (hsel ^ ((r >> 2) & 1)));
                uint32_t bh[4], bl[4];
                ldsm4(bh, stg + 16384 + off);
                ldsm4(bl, stg + 24576 + off);
                uint32_t b0h[2] = {bh[0], bh[2]}, b1h[2] = {bh[1], bh[3]};
                uint32_t b0l[2] = {bl[0], bl[2]}, b1l[2] = {bl[1], bl[3]};
#pragma unroll
                for (int mt = 0; mt < 2; ++mt) {
                    mma_bf16(acc[mt][2 * g],     ah[mt], b0h);
                    mma_bf16(acc[mt][2 * g + 1], ah[mt], b1h);
                    mma_bf16(acc[mt][2 * g],     ah[mt], b0l);
                    mma_bf16(acc[mt][2 * g + 1], ah[mt], b1l);
                    mma_bf16(acc[mt][2 * g],     al[mt], b0h);
                    mma_bf16(acc[mt][2 * g + 1], al[mt], b1h);
                }
            }
        }
        __syncthreads();
    }
#undef ISSUE

    /* ---- epilogue: frag (mt, f) rows m..m+8, cols n..n+1 ---- */
#pragma unroll
    for (int mt = 0; mt < 2; ++mt) {
#pragma unroll
        for (int f = 0; f < 8; ++f) {
            const int n = n0 + wn + (f >> 1) * 16 + (f & 1) * 8 + (lane & 3) * 2;
            const float2 bv = *(const float2*)&bias[n];
#pragma unroll
            for (int hrow = 0; hrow < 2; ++hrow) {
                const int m = m0 + wm + mt * 16 + (lane >> 2) + hrow * 8;
                float vx = acc[mt][f][hrow * 2 + 0] + bv.x;
                float vy = acc[mt][f][hrow * 2 + 1] + bv.y;
                if (MODE == 0) {
                    const int sel = n >> 9;
                    const int h = (n >> 5) & 15, d = n & 31;
                    if (sel == 0) { vx *= SCALE_F; vy *= SCALE_F; }
                    float* dst = (sel == 0) ? g_q : ((sel == 1) ? g_k : g_v);
                    *(float2*)&dst[(((size_t)(m >> 6) * NH + h) * NTOK + (m & 63)) * HD + d]
                        = make_float2(vx, vy);
                } else {
                    *(float2*)&out[(size_t)m * DIMC + n] = make_float2(vx, vy);
                }
            }
        }
    }
}

/* ================= fused attention per (b,h) ============================= */
__global__ __launch_bounds__(256) void attn_kernel()
{
    const int bh = blockIdx.x;
    const int b = bh >> 4, h = bh & 15;

    __shared__ float qT[32][68];
    __shared__ float kT[32][68];
    __shared__ float vsm[64][32];
    __shared__ float Ss[64][65];

    const float* qg = g_q + (size_t)bh * (NTOK * HD);
    const float* kg = g_k + (size_t)bh * (NTOK * HD);
    const float* vg = g_v + (size_t)bh * (NTOK * HD);

    const int tid = threadIdx.x;
    for (int e = tid; e < NTOK * HD; e += 256) {
        int n = e >> 5, d = e & 31;
        qT[d][n] = qg[e];
        kT[d][n] = kg[e];
        ((float*)vsm)[e] = vg[e];
    }
    __syncthreads();

    const int ty = tid >> 4, tx = tid & 15;
    const int i0 = ty << 2, j0 = tx << 2;
    float s4[4][4];
#pragma unroll
    for (int i = 0; i < 4; i++)
#pragma unroll
        for (int j = 0; j < 4; j++) s4[i][j] = 0.0f;
#pragma unroll
    for (int kk = 0; kk < 32; kk++) {
        float4 qa = *(const float4*)&qT[kk][i0];
        float4 kb = *(const float4*)&kT[kk][j0];
        float af[4] = {qa.x, qa.y, qa.z, qa.w};
        float bf[4] = {kb.x, kb.y, kb.z, kb.w};
#pragma unroll
        for (int i = 0; i < 4; i++)
#pragma unroll
            for (int j = 0; j < 4; j++) s4[i][j] += af[i] * bf[j];
    }
    const float* bp = g_bias + (h << 12);
#pragma unroll
    for (int i = 0; i < 4; i++) {
        float4 bv = *(const float4*)&bp[(i0 + i) * 64 + j0];
        Ss[i0 + i][j0 + 0] = s4[i][0] + bv.x;
        Ss[i0 + i][j0 + 1] = s4[i][1] + bv.y;
        Ss[i0 + i][j0 + 2] = s4[i][2] + bv.z;
        Ss[i0 + i][j0 + 3] = s4[i][3] + bv.w;
    }
    __syncthreads();

    const int r   = tid >> 2;
    const int seg = tid & 3;
    float* row = &Ss[0][0] + r * 65;
    float mx = -1e30f;
#pragma unroll
    for (int j = 0; j < 16; j++) mx = fmaxf(mx, row[seg * 16 + j]);
    mx = fmaxf(mx, __shfl_xor_sync(0xffffffffu, mx, 1));
    mx = fmaxf(mx, __shfl_xor_sync(0xffffffffu, mx, 2));
    float ev[16];
    float sum = 0.0f;
#pragma unroll
    for (int j = 0; j < 16; j++) { ev[j] = __expf(row[seg * 16 + j] - mx); sum += ev[j]; }
    sum += __shfl_xor_sync(0xffffffffu, sum, 1);
    sum += __shfl_xor_sync(0xffffffffu, sum, 2);
    float inv = 1.0f / sum;
#pragma unroll
    for (int j = 0; j < 16; j++) row[seg * 16 + j] = ev[j] * inv;
    __syncthreads();

    const int d0 = seg << 3;
    float oa[8];
#pragma unroll
    for (int i = 0; i < 8; i++) oa[i] = 0.0f;
#pragma unroll 8
    for (int j = 0; j < 64; j++) {
        float p = Ss[r][j];
        float4 v0 = *(const float4*)&vsm[j][d0];
        float4 v1 = *(const float4*)&vsm[j][d0 + 4];
        oa[0] += p * v0.x; oa[1] += p * v0.y; oa[2] += p * v0.z; oa[3] += p * v0.w;
        oa[4] += p * v1.x; oa[5] += p * v1.y; oa[6] += p * v1.z; oa[7] += p * v1.w;
    }
    /* write split bf16 directly for the proj GEMM */
    unsigned short hs[8], ls[8];
#pragma unroll
    for (int i = 0; i < 8; i++) split1(oa[i], hs[i], ls[i]);
    uint4 H = make_uint4((uint32_t)hs[0] | ((uint32_t)hs[1] << 16),
                         (uint32_t)hs[2] | ((uint32_t)hs[3] << 16),
                         (uint32_t)hs[4] | ((uint32_t)hs[5] << 16),
                         (uint32_t)hs[6] | ((uint32_t)hs[7] << 16));
    uint4 L = make_uint4((uint32_t)ls[0] | ((uint32_t)ls[1] << 16),
                         (uint32_t)ls[2] | ((uint32_t)ls[3] << 16),
                         (uint32_t)ls[4] | ((uint32_t)ls[5] << 16),
                         (uint32_t)ls[6] | ((uint32_t)ls[7] << 16));
    size_t ob = (size_t)(b * NTOK + r) * DIMC + h * HD + d0;
    *(uint4*)&g_atthi[ob] = H;
    *(uint4*)&g_attlo[ob] = L;
}

/* ========================================================================= */
extern "C" void kernel_launch(void* const* d_in, const int* in_sizes, int n_in,
                              void* d_out, int out_size)
{
    (void)in_sizes; (void)n_in; (void)out_size;
    const float* x      = (const float*)d_in[0];
    const float* theta  = (const float*)d_in[1];
    const float* qkv_w  = (const float*)d_in[2];
    const float* qkv_b  = (const float*)d_in[3];
    const float* proj_w = (const float*)d_in[4];
    const float* proj_b = (const float*)d_in[5];
    const float* a_p    = (const float*)d_in[6];
    const float* b_p    = (const float*)d_in[7];
    const float* a_r    = (const float*)d_in[8];
    const float* b_r    = (const float*)d_in[9];
    float* out = (float*)d_out;

    static int smem_set = 0;
    if (!smem_set) {
        cudaFuncSetAttribute(mma_gemm<0>, cudaFuncAttributeMaxDynamicSharedMemorySize, SMEM_TOTAL);
        cudaFuncSetAttribute(mma_gemm<1>, cudaFuncAttributeMaxDynamicSharedMemorySize, SMEM_TOTAL);
        smem_set = 1;
    }

    bias_kernel<<<256, 256>>>(theta, a_p, b_p, a_r, b_r);
    split_kernel<<<(M_TOT * DIMC / 4 + 255) / 256, 256>>>(x, 0, M_TOT * DIMC / 4);
    split_kernel<<<(3 * DIMC * DIMC / 4 + 255) / 256, 256>>>(qkv_w, 1, 3 * DIMC * DIMC / 4);
    split_kernel<<<(DIMC * DIMC / 4 + 255) / 256, 256>>>(proj_w, 2, DIMC * DIMC / 4);
    mma_gemm<0><<<dim3(12, 512), 256, SMEM_TOTAL>>>(qkv_b, nullptr);
    attn_kernel<<<B_WIN * NH, 256>>>();
    mma_gemm<1><<<dim3(4, 512), 256, SMEM_TOTAL>>>(proj_b, out);
}

// round 6
// speedup vs baseline: 2.0592x; 1.0745x over previous
#include <cuda_runtime.h>
#include <cuda_bf16.h>
#include <stdint.h>
#include <math.h>

#define B_WIN   1024
#define NTOK    64
#define DIMC    512
#define NH      16
#define HD      32
#define M_TOT   (B_WIN * NTOK)           /* 65536 */
#define SCALE_F 0.17677669529663687f     /* 32^-0.5 */

/* ---------------- static device scratch (no allocation) ------------------ */
__device__ float g_bias[NH * NTOK * NTOK];
__device__ __nv_bfloat16 g_xhi[(size_t)M_TOT * DIMC];
__device__ __nv_bfloat16 g_xlo[(size_t)M_TOT * DIMC];
__device__ __nv_bfloat16 g_atthi[(size_t)M_TOT * DIMC];   /* [b*64+tok][h*32+d] */
__device__ __nv_bfloat16 g_attlo[(size_t)M_TOT * DIMC];
__device__ __nv_bfloat16 g_wqhi[3 * DIMC * DIMC];
__device__ __nv_bfloat16 g_wqlo[3 * DIMC * DIMC];
__device__ __nv_bfloat16 g_wphi[DIMC * DIMC];
__device__ __nv_bfloat16 g_wplo[DIMC * DIMC];
/* q/k/v as bf16 hi/lo, layout [b][h][tok][d] */
__device__ __nv_bfloat16 g_qhi[(size_t)M_TOT * DIMC];
__device__ __nv_bfloat16 g_qlo[(size_t)M_TOT * DIMC];
__device__ __nv_bfloat16 g_khi[(size_t)M_TOT * DIMC];
__device__ __nv_bfloat16 g_klo[(size_t)M_TOT * DIMC];
__device__ __nv_bfloat16 g_vhi[(size_t)M_TOT * DIMC];
__device__ __nv_bfloat16 g_vlo[(size_t)M_TOT * DIMC];

/* ---------------- portable tensor-core helpers (sm_80+) ------------------ */
__device__ __forceinline__ uint32_t smem_u32(const void* p) {
    return (uint32_t)__cvta_generic_to_shared(p);
}
__device__ __forceinline__ void ldsm4(uint32_t* r, uint32_t addr) {
    asm volatile("ldmatrix.sync.aligned.m8n8.x4.shared.b16 {%0,%1,%2,%3}, [%4];"
        : "=r"(r[0]), "=r"(r[1]), "=r"(r[2]), "=r"(r[3]) : "r"(addr));
}
__device__ __forceinline__ void ldsm4t(uint32_t* r, uint32_t addr) {
    asm volatile("ldmatrix.sync.aligned.m8n8.x4.trans.shared.b16 {%0,%1,%2,%3}, [%4];"
        : "=r"(r[0]), "=r"(r[1]), "=r"(r[2]), "=r"(r[3]) : "r"(addr));
}
__device__ __forceinline__ void mma_bf16(float* d, const uint32_t* a, const uint32_t* b) {
    asm volatile("mma.sync.aligned.m16n8k16.row.col.f32.bf16.bf16.f32 "
        "{%0,%1,%2,%3}, {%4,%5,%6,%7}, {%8,%9}, {%0,%1,%2,%3};"
        : "+f"(d[0]), "+f"(d[1]), "+f"(d[2]), "+f"(d[3])
        : "r"(a[0]), "r"(a[1]), "r"(a[2]), "r"(a[3]), "r"(b[0]), "r"(b[1]));
}
#define CP_ASYNC16(dst, src) \
    asm volatile("cp.async.cg.shared.global [%0], [%1], 16;" :: "r"(dst), "l"(src))
#define CP_COMMIT()  asm volatile("cp.async.commit_group;" ::: "memory")
#define CP_WAIT1()   asm volatile("cp.async.wait_group 1;" ::: "memory")
#define CP_WAIT0()   asm volatile("cp.async.wait_group 0;" ::: "memory")

/* ================= bias table ============================================ */
__global__ void bias_kernel(const float* __restrict__ theta_max,
                            const float* __restrict__ a_p, const float* __restrict__ b_p,
                            const float* __restrict__ a_r, const float* __restrict__ b_r)
{
    int idx = blockIdx.x * 256 + threadIdx.x;
    int h = idx >> 12;
    int ij = idx & 4095;
    int i = ij >> 6, j = ij & 63;
    int dr = (i >> 3) - (j >> 3);
    int dc = (i & 7) - (j & 7);
    int idx_r  = ((dr % 15) + 15) % 15;
    int idx_az = ((dc % 15) + 15) % 15;
    float az = (float)dc * (2.0f * 3.14159265358979323846f / 32.0f);
    float ra = (float)dr * (theta_max[0] / 32.0f);
    g_bias[idx] = a_p[idx_az * NH + h] * cosf(az) + b_p[idx_az * NH + h] * sinf(az)
                + a_r[idx_r  * NH + h] * cosf(ra) + b_r[idx_r  * NH + h] * sinf(ra);
}

/* ================= fp32 -> bf16 hi/lo split ============================== */
__device__ __forceinline__ void split1(float x, unsigned short& h, unsigned short& l) {
    __nv_bfloat16 hb = __float2bfloat16(x);
    float res = x - __bfloat162float(hb);
    h = __bfloat16_as_ushort(hb);
    l = __bfloat16_as_ushort(__float2bfloat16(res));
}
__global__ void split_kernel(const float* __restrict__ src, int which, int n4)
{
    int i = blockIdx.x * 256 + threadIdx.x;
    if (i >= n4) return;
    float4 v = ((const float4*)src)[i];
    unsigned short h0, h1, h2, h3, l0, l1, l2, l3;
    split1(v.x, h0, l0); split1(v.y, h1, l1);
    split1(v.z, h2, l2); split1(v.w, h3, l3);
    uint2 H = make_uint2((uint32_t)h0 | ((uint32_t)h1 << 16),
                         (uint32_t)h2 | ((uint32_t)h3 << 16));
    uint2 L = make_uint2((uint32_t)l0 | ((uint32_t)l1 << 16),
                         (uint32_t)l2 | ((uint32_t)l3 << 16));
    __nv_bfloat16 *hp, *lp;
    if (which == 0)      { hp = g_xhi; lp = g_xlo; }
    else if (which == 1) { hp = g_wqhi; lp = g_wqlo; }
    else                 { hp = g_wphi; lp = g_wplo; }
    ((uint2*)hp)[i] = H;
    ((uint2*)lp)[i] = L;
}

/* ================= mma.sync split-bf16 GEMM ============================== */
/* C[M,N] = A[M,512] * W[N,512]^T + bias.  CTA tile 128x128, 8 warps.       */
/* MODE 0: A=g_x*, W=g_wq* (N=1536) -> scatter q/k/v bf16 hi/lo (+SCALE q). */
/* MODE 1: A=g_att*, W=g_wp* (N=512) -> out (fp32).                         */
#define STAGE_B 32768
#define SMEM_TOTAL (2 * STAGE_B)

template<int MODE>
__global__ __launch_bounds__(256, 2) void mma_gemm(const float* __restrict__ bias,
                                                   float* __restrict__ out)
{
    extern __shared__ char smem[];
    const uint32_t sb = smem_u32(smem);
    const int tid = threadIdx.x, wid = tid >> 5, lane = tid & 31;
    const int m0 = blockIdx.y << 7;
    const int n0 = blockIdx.x << 7;
    const int wm = (wid & 3) << 5;          /* warp row offset (0..96)  */
    const int wn = (wid >> 2) << 6;         /* warp col offset (0/64)   */

    const __nv_bfloat16* __restrict__ Ahi = (MODE == 0) ? g_xhi : g_atthi;
    const __nv_bfloat16* __restrict__ Alo = (MODE == 0) ? g_xlo : g_attlo;
    const __nv_bfloat16* __restrict__ Whi = (MODE == 0) ? g_wqhi : g_wphi;
    const __nv_bfloat16* __restrict__ Wlo = (MODE == 0) ? g_wqlo : g_wplo;

    float acc[2][8][4];
#pragma unroll
    for (int a = 0; a < 2; a++)
#pragma unroll
        for (int b = 0; b < 8; b++)
#pragma unroll
            for (int c = 0; c < 4; c++) acc[a][b][c] = 0.0f;

    const int c_r0   = tid >> 2,          c_q0 = tid & 3;
    const int c_r1   = (tid + 256) >> 2;
    const int ksl0 = c_q0 >> 1, half0 = c_q0 & 1;
    const uint32_t off0 = 16u * (ksl0 * 256 + c_r0 * 2 + (half0 ^ ((c_r0 >> 2) & 1)));
    const uint32_t off1 = 16u * (ksl0 * 256 + c_r1 * 2 + (half0 ^ ((c_r1 >> 2) & 1)));
    const int kc0 = ksl0 * 16 + half0 * 8;

#define ISSUE(ch) do {                                                         \
    const uint32_t stg = sb + ((ch) & 1) * STAGE_B;                            \
    const int kk = ((ch) << 5) + kc0;                                          \
    size_t a0 = (size_t)(m0 + c_r0) * DIMC + kk;                               \
    size_t a1 = (size_t)(m0 + c_r1) * DIMC + kk;                               \
    size_t b0 = (size_t)(n0 + c_r0) * DIMC + kk;                               \
    size_t b1 = (size_t)(n0 + c_r1) * DIMC + kk;                               \
    CP_ASYNC16(stg + off0,         Ahi + a0);                                  \
    CP_ASYNC16(stg + off1,         Ahi + a1);                                  \
    CP_ASYNC16(stg + 8192  + off0, Alo + a0);                                  \
    CP_ASYNC16(stg + 8192  + off1, Alo + a1);                                  \
    CP_ASYNC16(stg + 16384 + off0, Whi + b0);                                  \
    CP_ASYNC16(stg + 16384 + off1, Whi + b1);                                  \
    CP_ASYNC16(stg + 24576 + off0, Wlo + b0);                                  \
    CP_ASYNC16(stg + 24576 + off1, Wlo + b1);                                  \
    CP_COMMIT();                                                               \
} while (0)

    ISSUE(0);
    const int rloc = lane & 15, hsel = lane >> 4;
    for (int ch = 0; ch < 16; ++ch) {
        if (ch < 15) { ISSUE(ch + 1); CP_WAIT1(); }
        else         { CP_WAIT0(); }
        __syncthreads();
        const uint32_t stg = sb + (ch & 1) * STAGE_B;
#pragma unroll
        for (int ks = 0; ks < 2; ++ks) {
            uint32_t ah[2][4], al[2][4];
#pragma unroll
            for (int mt = 0; mt < 2; ++mt) {
                int r = wm + mt * 16 + rloc;
                uint32_t off = 16u * (ks * 256 + r * 2 + (hsel ^ ((r >> 2) & 1)));
                ldsm4(ah[mt], stg + off);
                ldsm4(al[mt], stg + 8192 + off);
            }
#pragma unroll
            for (int g = 0; g < 4; ++g) {
                int r = wn + g * 16 + rloc;
                uint32_t off = 16u * (ks * 256 + r * 2 + (hsel ^ ((r >> 2) & 1)));
                uint32_t bh[4], bl[4];
                ldsm4(bh, stg + 16384 + off);
                ldsm4(bl, stg + 24576 + off);
                uint32_t b0h[2] = {bh[0], bh[2]}, b1h[2] = {bh[1], bh[3]};
                uint32_t b0l[2] = {bl[0], bl[2]}, b1l[2] = {bl[1], bl[3]};
#pragma unroll
                for (int mt = 0; mt < 2; ++mt) {
                    mma_bf16(acc[mt][2 * g],     ah[mt], b0h);
                    mma_bf16(acc[mt][2 * g + 1], ah[mt], b1h);
                    mma_bf16(acc[mt][2 * g],     ah[mt], b0l);
                    mma_bf16(acc[mt][2 * g + 1], ah[mt], b1l);
                    mma_bf16(acc[mt][2 * g],     al[mt], b0h);
                    mma_bf16(acc[mt][2 * g + 1], al[mt], b1h);
                }
            }
        }
        __syncthreads();
    }
#undef ISSUE

    /* ---- epilogue ---- */
#pragma unroll
    for (int mt = 0; mt < 2; ++mt) {
#pragma unroll
        for (int f = 0; f < 8; ++f) {
            const int n = n0 + wn + (f >> 1) * 16 + (f & 1) * 8 + (lane & 3) * 2;
            const float2 bv = *(const float2*)&bias[n];
#pragma unroll
            for (int hrow = 0; hrow < 2; ++hrow) {
                const int m = m0 + wm + mt * 16 + (lane >> 2) + hrow * 8;
                float vx = acc[mt][f][hrow * 2 + 0] + bv.x;
                float vy = acc[mt][f][hrow * 2 + 1] + bv.y;
                if (MODE == 0) {
                    const int sel = n >> 9;
                    const int h = (n >> 5) & 15, d = n & 31;
                    if (sel == 0) { vx *= SCALE_F; vy *= SCALE_F; }
                    unsigned short hx, lx, hy, ly;
                    split1(vx, hx, lx); split1(vy, hy, ly);
                    uint32_t H = (uint32_t)hx | ((uint32_t)hy << 16);
                    uint32_t L = (uint32_t)lx | ((uint32_t)ly << 16);
                    __nv_bfloat16 *dh, *dl;
                    if (sel == 0)      { dh = g_qhi; dl = g_qlo; }
                    else if (sel == 1) { dh = g_khi; dl = g_klo; }
                    else               { dh = g_vhi; dl = g_vlo; }
                    size_t base = (((size_t)(m >> 6) * NH + h) * NTOK + (m & 63)) * HD + d;
                    *(uint32_t*)&dh[base] = H;
                    *(uint32_t*)&dl[base] = L;
                } else {
                    *(float2*)&out[(size_t)m * DIMC + n] = make_float2(vx, vy);
                }
            }
        }
    }
}

/* ================= tensor-core attention ================================= */
/* CTA = (b, head-pair). 8 warps: warp -> (head = 2*hp + w/4, mtile = w%4). */
/* Warp computes 16 rows of S (16x64), softmax, then O (16x32).             */
#define VROWB 80   /* padded v smem row bytes (32 bf16 = 64B + 16B pad) */

__global__ __launch_bounds__(256, 2) void attn_mma_kernel()
{
    const int cta = blockIdx.x;           /* 0 .. 8191 */
    const int b = cta >> 3, hp = cta & 7;
    const int tid = threadIdx.x, wid = tid >> 5, lane = tid & 31;
    const int h2 = wid >> 2;
    const int h  = hp * 2 + h2;
    const int m0 = (wid & 3) << 4;

    __shared__ __align__(16) unsigned char vbuf[2][2][64 * VROWB];

    /* stage v hi/lo for both heads: [tok][d] rows padded to 80B */
    {
        const size_t vb0 = ((size_t)b * NH + hp * 2) * (NTOK * HD);
        const uint32_t* sh = (const uint32_t*)g_vhi + vb0 / 2;
        const uint32_t* sl = (const uint32_t*)g_vlo + vb0 / 2;
        for (int e = tid; e < 2048; e += 256) {        /* 2 heads x 1024 u32 */
            int hh = e >> 10, e2 = e & 1023;
            int row = e2 >> 4, c = e2 & 15;
            uint32_t off = (uint32_t)(row * VROWB + c * 4);
            *(uint32_t*)&vbuf[hh][0][off] = sh[hh * 1024 + row * 16 + c];
            *(uint32_t*)&vbuf[hh][1][off] = sl[hh * 1024 + row * 16 + c];
        }
    }
    __syncthreads();

    const size_t qkb = ((size_t)b * NH + h) * (NTOK * HD);
    const __nv_bfloat16* qh = g_qhi + qkb;
    const __nv_bfloat16* ql = g_qlo + qkb;
    const __nv_bfloat16* kh = g_khi + qkb;
    const __nv_bfloat16* kl = g_klo + qkb;

    const int rA = m0 + (lane >> 2);      /* local token row */
    const int cp = (lane & 3) << 1;       /* fragment col pair */

    /* q fragments (A operand), 2 k-tiles of 16 over d=32 */
    uint32_t aqh[2][4], aql[2][4];
#pragma unroll
    for (int kt = 0; kt < 2; ++kt) {
        const int kc = kt * 16 + cp;
        aqh[kt][0] = *(const uint32_t*)&qh[(size_t)rA * HD + kc];
        aqh[kt][1] = *(const uint32_t*)&qh[(size_t)(rA + 8) * HD + kc];
        aqh[kt][2] = *(const uint32_t*)&qh[(size_t)rA * HD + kc + 8];
        aqh[kt][3] = *(const uint32_t*)&qh[(size_t)(rA + 8) * HD + kc + 8];
        aql[kt][0] = *(const uint32_t*)&ql[(size_t)rA * HD + kc];
        aql[kt][1] = *(const uint32_t*)&ql[(size_t)(rA + 8) * HD + kc];
        aql[kt][2] = *(const uint32_t*)&ql[(size_t)rA * HD + kc + 8];
        aql[kt][3] = *(const uint32_t*)&ql[(size_t)(rA + 8) * HD + kc + 8];
    }

    /* S = q k^T (3-term split), 8 n-tiles of 8 cols */
    float sc[8][4];
#pragma unroll
    for (int nt = 0; nt < 8; ++nt) { sc[nt][0] = sc[nt][1] = sc[nt][2] = sc[nt][3] = 0.0f; }
    const int nrow = (lane >> 2);
#pragma unroll
    for (int nt = 0; nt < 8; ++nt) {
        const size_t krow = (size_t)(nt * 8 + nrow) * HD;
#pragma unroll
        for (int kt = 0; kt < 2; ++kt) {
            const int kc = kt * 16 + cp;
            uint32_t bh[2], bl[2];
            bh[0] = *(const uint32_t*)&kh[krow + kc];
            bh[1] = *(const uint32_t*)&kh[krow + kc + 8];
            bl[0] = *(const uint32_t*)&kl[krow + kc];
            bl[1] = *(const uint32_t*)&kl[krow + kc + 8];
            mma_bf16(sc[nt], aqh[kt], bh);
            mma_bf16(sc[nt], aqh[kt], bl);
            mma_bf16(sc[nt], aql[kt], bh);
        }
    }

    /* + bias */
    const float* bp = g_bias + (h << 12);
#pragma unroll
    for (int nt = 0; nt < 8; ++nt) {
        float2 bA = *(const float2*)&bp[rA * 64 + nt * 8 + cp];
        float2 bB = *(const float2*)&bp[(rA + 8) * 64 + nt * 8 + cp];
        sc[nt][0] += bA.x; sc[nt][1] += bA.y;
        sc[nt][2] += bB.x; sc[nt][3] += bB.y;
    }

    /* softmax (rows rA and rA+8), 4-lane groups */
    float mA = -1e30f, mB = -1e30f;
#pragma unroll
    for (int nt = 0; nt < 8; ++nt) {
        mA = fmaxf(mA, fmaxf(sc[nt][0], sc[nt][1]));
        mB = fmaxf(mB, fmaxf(sc[nt][2], sc[nt][3]));
    }
    mA = fmaxf(mA, __shfl_xor_sync(0xffffffffu, mA, 1));
    mA = fmaxf(mA, __shfl_xor_sync(0xffffffffu, mA, 2));
    mB = fmaxf(mB, __shfl_xor_sync(0xffffffffu, mB, 1));
    mB = fmaxf(mB, __shfl_xor_sync(0xffffffffu, mB, 2));
    float sA = 0.0f, sB = 0.0f;
#pragma unroll
    for (int nt = 0; nt < 8; ++nt) {
        sc[nt][0] = __expf(sc[nt][0] - mA); sA += sc[nt][0];
        sc[nt][1] = __expf(sc[nt][1] - mA); sA += sc[nt][1];
        sc[nt][2] = __expf(sc[nt][2] - mB); sB += sc[nt][2];
        sc[nt][3] = __expf(sc[nt][3] - mB); sB += sc[nt][3];
    }
    sA += __shfl_xor_sync(0xffffffffu, sA, 1);
    sA += __shfl_xor_sync(0xffffffffu, sA, 2);
    sB += __shfl_xor_sync(0xffffffffu, sB, 1);
    sB += __shfl_xor_sync(0xffffffffu, sB, 2);
    const float iA = 1.0f / sA, iB = 1.0f / sB;
#pragma unroll
    for (int nt = 0; nt < 8; ++nt) {
        sc[nt][0] *= iA; sc[nt][1] *= iA;
        sc[nt][2] *= iB; sc[nt][3] *= iB;
    }

    /* O = P V : P (16x64) from registers (2-term split), V via ldmatrix.trans */
    float oc[4][4];
#pragma unroll
    for (int nt = 0; nt < 4; ++nt) { oc[nt][0] = oc[nt][1] = oc[nt][2] = oc[nt][3] = 0.0f; }
    const uint32_t vh_base = smem_u32(&vbuf[h2][0][0]);
    const uint32_t vl_base = smem_u32(&vbuf[h2][1][0]);
    const uint32_t lrow = (lane & 7) + ((lane >> 3) & 1) * 8;
    const uint32_t lcol16 = (lane >> 4);    /* 0/1 : n-tile within ldsm4 */
#pragma unroll
    for (int kt = 0; kt < 4; ++kt) {
        /* P fragments for j in [kt*16, kt*16+16) */
        uint32_t ph[4], pl[4];
#pragma unroll
        for (int half = 0; half < 2; ++half) {
            const int nt = 2 * kt + half;
            float p0 = sc[nt][0], p1 = sc[nt][1], p2 = sc[nt][2], p3 = sc[nt][3];
            __nv_bfloat16 h0 = __float2bfloat16(p0), h1 = __float2bfloat16(p1);
            __nv_bfloat16 h2b = __float2bfloat16(p2), h3 = __float2bfloat16(p3);
            ph[half * 2 + 0] = (uint32_t)__bfloat16_as_ushort(h0)
                             | ((uint32_t)__bfloat16_as_ushort(h1) << 16);
            ph[half * 2 + 1] = (uint32_t)__bfloat16_as_ushort(h2b)
                             | ((uint32_t)__bfloat16_as_ushort(h3) << 16);
            __nv_bfloat16 l0 = __float2bfloat16(p0 - __bfloat162float(h0));
            __nv_bfloat16 l1 = __float2bfloat16(p1 - __bfloat162float(h1));
            __nv_bfloat16 l2 = __float2bfloat16(p2 - __bfloat162float(h2b));
            __nv_bfloat16 l3 = __float2bfloat16(p3 - __bfloat162float(h3));
            pl[half * 2 + 0] = (uint32_t)__bfloat16_as_ushort(l0)
                             | ((uint32_t)__bfloat16_as_ushort(l1) << 16);
            pl[half * 2 + 1] = (uint32_t)__bfloat16_as_ushort(l2)
                             | ((uint32_t)__bfloat16_as_ushort(l3) << 16);
        }
        /* reorder to A-frag: a0=(rA,klo) a1=(rB,klo) a2=(rA,khi) a3=(rB,khi) */
        uint32_t pa_h[4] = {ph[0], ph[1], ph[2], ph[3]};
        uint32_t pa_l[4] = {pl[0], pl[1], pl[2], pl[3]};

        /* V b-fragments: 4 n-tiles (d), 2 ldsm4.trans each for hi/lo */
        uint32_t vh0[4], vh1[4], vl0[4], vl1[4];
        const uint32_t roff = (uint32_t)((kt * 16 + lrow) * VROWB);
        ldsm4t(vh0, vh_base + roff + lcol16 * 16);
        ldsm4t(vh1, vh_base + roff + (lcol16 + 2) * 16);
        ldsm4t(vl0, vl_base + roff + lcol16 * 16);
        ldsm4t(vl1, vl_base + roff + (lcol16 + 2) * 16);
        uint32_t bvh[4][2] = {{vh0[0], vh0[1]}, {vh0[2], vh0[3]},
                              {vh1[0], vh1[1]}, {vh1[2], vh1[3]}};
        uint32_t bvl[4][2] = {{vl0[0], vl0[1]}, {vl0[2], vl0[3]},
                              {vl1[0], vl1[1]}, {vl1[2], vl1[3]}};
#pragma unroll
        for (int nt = 0; nt < 4; ++nt) {
            mma_bf16(oc[nt], pa_h, bvh[nt]);
            mma_bf16(oc[nt], pa_h, bvl[nt]);
            mma_bf16(oc[nt], pa_l, bvh[nt]);
        }
    }

    /* epilogue: split O to bf16 hi/lo into g_att* [b*64+tok][h*32+d] */
    const size_t obA = ((size_t)(b * NTOK + rA)) * DIMC + h * HD;
    const size_t obB = obA + (size_t)8 * DIMC;
#pragma unroll
    for (int nt = 0; nt < 4; ++nt) {
        const int d = nt * 8 + cp;
        unsigned short hx, lx, hy, ly;
        split1(oc[nt][0], hx, lx); split1(oc[nt][1], hy, ly);
        *(uint32_t*)&g_atthi[obA + d] = (uint32_t)hx | ((uint32_t)hy << 16);
        *(uint32_t*)&g_attlo[obA + d] = (uint32_t)lx | ((uint32_t)ly << 16);
        split1(oc[nt][2], hx, lx); split1(oc[nt][3], hy, ly);
        *(uint32_t*)&g_atthi[obB + d] = (uint32_t)hx | ((uint32_t)hy << 16);
        *(uint32_t*)&g_attlo[obB + d] = (uint32_t)lx | ((uint32_t)ly << 16);
    }
}

/* ========================================================================= */
extern "C" void kernel_launch(void* const* d_in, const int* in_sizes, int n_in,
                              void* d_out, int out_size)
{
    (void)in_sizes; (void)n_in; (void)out_size;
    const float* x      = (const float*)d_in[0];
    const float* theta  = (const float*)d_in[1];
    const float* qkv_b  = (const float*)d_in[3];
    const float* proj_b = (const float*)d_in[5];
    const float* a_p    = (const float*)d_in[6];
    const float* b_p    = (const float*)d_in[7];
    const float* a_r    = (const float*)d_in[8];
    const float* b_r    = (const float*)d_in[9];
    const float* qkv_w  = (const float*)d_in[2];
    const float* proj_w = (const float*)d_in[4];
    float* out = (float*)d_out;

    static int smem_set = 0;
    if (!smem_set) {
        cudaFuncSetAttribute(mma_gemm<0>, cudaFuncAttributeMaxDynamicSharedMemorySize, SMEM_TOTAL);
        cudaFuncSetAttribute(mma_gemm<1>, cudaFuncAttributeMaxDynamicSharedMemorySize, SMEM_TOTAL);
        smem_set = 1;
    }

    bias_kernel<<<256, 256>>>(theta, a_p, b_p, a_r, b_r);
    split_kernel<<<(M_TOT * DIMC / 4 + 255) / 256, 256>>>(x, 0, M_TOT * DIMC / 4);
    split_kernel<<<(3 * DIMC * DIMC / 4 + 255) / 256, 256>>>(qkv_w, 1, 3 * DIMC * DIMC / 4);
    split_kernel<<<(DIMC * DIMC / 4 + 255) / 256, 256>>>(proj_w, 2, DIMC * DIMC / 4);
    mma_gemm<0><<<dim3(12, 512), 256, SMEM_TOTAL>>>(qkv_b, nullptr);
    attn_mma_kernel<<<B_WIN * 8, 256>>>();
    mma_gemm<1><<<dim3(4, 512), 256, SMEM_TOTAL>>>(proj_b, out);
}

// round 7
// speedup vs baseline: 4.1604x; 2.0204x over previous
#include <cuda_runtime.h>
#include <cuda_fp16.h>
#include <stdint.h>
#include <math.h>

#define B_WIN   1024
#define NTOK    64
#define DIMC    512
#define NH      16
#define HD      32
#define M_TOT   (B_WIN * NTOK)           /* 65536 */
#define SCALE_F 0.17677669529663687f     /* 32^-0.5 */

/* ---------------- static device scratch (no allocation) ------------------ */
__device__ float g_bias[NH * NTOK * NTOK];
__device__ __half g_x[(size_t)M_TOT * DIMC];
__device__ __half g_att[(size_t)M_TOT * DIMC];     /* [b*64+tok][h*32+d] */
__device__ __half g_wq[3 * DIMC * DIMC];
__device__ __half g_wp[DIMC * DIMC];
/* q/k/v fp16, layout [b][h][tok][d] */
__device__ __half g_q[(size_t)M_TOT * DIMC];
__device__ __half g_k[(size_t)M_TOT * DIMC];
__device__ __half g_v[(size_t)M_TOT * DIMC];

/* ---------------- portable tensor-core helpers (sm_80+) ------------------ */
__device__ __forceinline__ uint32_t smem_u32(const void* p) {
    return (uint32_t)__cvta_generic_to_shared(p);
}
__device__ __forceinline__ void ldsm4(uint32_t* r, uint32_t addr) {
    asm volatile("ldmatrix.sync.aligned.m8n8.x4.shared.b16 {%0,%1,%2,%3}, [%4];"
        : "=r"(r[0]), "=r"(r[1]), "=r"(r[2]), "=r"(r[3]) : "r"(addr));
}
__device__ __forceinline__ void ldsm4t(uint32_t* r, uint32_t addr) {
    asm volatile("ldmatrix.sync.aligned.m8n8.x4.trans.shared.b16 {%0,%1,%2,%3}, [%4];"
        : "=r"(r[0]), "=r"(r[1]), "=r"(r[2]), "=r"(r[3]) : "r"(addr));
}
__device__ __forceinline__ void mma_f16(float* d, const uint32_t* a, const uint32_t* b) {
    asm volatile("mma.sync.aligned.m16n8k16.row.col.f32.f16.f16.f32 "
        "{%0,%1,%2,%3}, {%4,%5,%6,%7}, {%8,%9}, {%0,%1,%2,%3};"
        : "+f"(d[0]), "+f"(d[1]), "+f"(d[2]), "+f"(d[3])
        : "r"(a[0]), "r"(a[1]), "r"(a[2]), "r"(a[3]), "r"(b[0]), "r"(b[1]));
}
#define CP_ASYNC16(dst, src) \
    asm volatile("cp.async.cg.shared.global [%0], [%1], 16;" :: "r"(dst), "l"(src))
#define CP_COMMIT()  asm volatile("cp.async.commit_group;" ::: "memory")
#define CP_WAIT1()   asm volatile("cp.async.wait_group 1;" ::: "memory")
#define CP_WAIT0()   asm volatile("cp.async.wait_group 0;" ::: "memory")

__device__ __forceinline__ uint32_t pack_h2(float a, float b) {
    __half ha = __float2half(a), hb = __float2half(b);
    return (uint32_t)__half_as_ushort(ha) | ((uint32_t)__half_as_ushort(hb) << 16);
}

/* ================= bias table ============================================ */
__global__ void bias_kernel(const float* __restrict__ theta_max,
                            const float* __restrict__ a_p, const float* __restrict__ b_p,
                            const float* __restrict__ a_r, const float* __restrict__ b_r)
{
    int idx = blockIdx.x * 256 + threadIdx.x;
    int h = idx >> 12;
    int ij = idx & 4095;
    int i = ij >> 6, j = ij & 63;
    int dr = (i >> 3) - (j >> 3);
    int dc = (i & 7) - (j & 7);
    int idx_r  = ((dr % 15) + 15) % 15;
    int idx_az = ((dc % 15) + 15) % 15;
    float az = (float)dc * (2.0f * 3.14159265358979323846f / 32.0f);
    float ra = (float)dr * (theta_max[0] / 32.0f);
    g_bias[idx] = a_p[idx_az * NH + h] * cosf(az) + b_p[idx_az * NH + h] * sinf(az)
                + a_r[idx_r  * NH + h] * cosf(ra) + b_r[idx_r  * NH + h] * sinf(ra);
}

/* ================= fp32 -> fp16 convert ================================== */
__global__ void cvt_kernel(const float* __restrict__ src, int which, int n4)
{
    int i = blockIdx.x * 256 + threadIdx.x;
    if (i >= n4) return;
    float4 v = ((const float4*)src)[i];
    uint2 H = make_uint2(pack_h2(v.x, v.y), pack_h2(v.z, v.w));
    __half* hp = (which == 0) ? g_x : ((which == 1) ? g_wq : g_wp);
    ((uint2*)hp)[i] = H;
}

/* ================= mma.sync fp16 GEMM ==================================== */
/* C[M,N] = A[M,512] * W[N,512]^T + bias.  CTA tile 128x128, 8 warps.       */
/* smem stage (16KB): A | W, each 128 rows x 32 fp16, 16B-chunk XOR swizzle */
/* MODE 0: A=g_x, W=g_wq (N=1536) -> scatter q/k/v fp16 (+SCALE on q).      */
/* MODE 1: A=g_att, W=g_wp (N=512) -> out (fp32).                           */
#define STAGE_B 16384
#define SMEM_TOTAL (2 * STAGE_B)

template<int MODE>
__global__ __launch_bounds__(256, 2) void mma_gemm(const float* __restrict__ bias,
                                                   float* __restrict__ out)
{
    extern __shared__ char smem[];
    const uint32_t sb = smem_u32(smem);
    const int tid = threadIdx.x, wid = tid >> 5, lane = tid & 31;
    const int m0 = blockIdx.y << 7;
    const int n0 = blockIdx.x << 7;
    const int wm = (wid & 3) << 5;          /* warp row offset (0..96)  */
    const int wn = (wid >> 2) << 6;         /* warp col offset (0/64)   */

    const __half* __restrict__ A = (MODE == 0) ? g_x : g_att;
    const __half* __restrict__ W = (MODE == 0) ? g_wq : g_wp;

    float acc[2][8][4];
#pragma unroll
    for (int a = 0; a < 2; a++)
#pragma unroll
        for (int b = 0; b < 8; b++)
#pragma unroll
            for (int c = 0; c < 4; c++) acc[a][b][c] = 0.0f;

    const int c_r0   = tid >> 2,          c_q0 = tid & 3;
    const int c_r1   = (tid + 256) >> 2;
    const int ksl0 = c_q0 >> 1, half0 = c_q0 & 1;
    const uint32_t off0 = 16u * (ksl0 * 256 + c_r0 * 2 + (half0 ^ ((c_r0 >> 2) & 1)));
    const uint32_t off1 = 16u * (ksl0 * 256 + c_r1 * 2 + (half0 ^ ((c_r1 >> 2) & 1)));
    const int kc0 = ksl0 * 16 + half0 * 8;

#define ISSUE(ch) do {                                                         \
    const uint32_t stg = sb + ((ch) & 1) * STAGE_B;                            \
    const int kk = ((ch) << 5) + kc0;                                          \
    size_t a0 = (size_t)(m0 + c_r0) * DIMC + kk;                               \
    size_t a1 = (size_t)(m0 + c_r1) * DIMC + kk;                               \
    size_t b0 = (size_t)(n0 + c_r0) * DIMC + kk;                               \
    size_t b1 = (size_t)(n0 + c_r1) * DIMC + kk;                               \
    CP_ASYNC16(stg + off0,        A + a0);                                     \
    CP_ASYNC16(stg + off1,        A + a1);                                     \
    CP_ASYNC16(stg + 8192 + off0, W + b0);                                     \
    CP_ASYNC16(stg + 8192 + off1, W + b1);                                     \
    CP_COMMIT();                                                               \
} while (0)

    ISSUE(0);
    const int rloc = lane & 15, hsel = lane >> 4;
    for (int ch = 0; ch < 16; ++ch) {
        if (ch < 15) { ISSUE(ch + 1); CP_WAIT1(); }
        else         { CP_WAIT0(); }
        __syncthreads();
        const uint32_t stg = sb + (ch & 1) * STAGE_B;
#pragma unroll
        for (int ks = 0; ks < 2; ++ks) {
            uint32_t ah[2][4];
#pragma unroll
            for (int mt = 0; mt < 2; ++mt) {
                int r = wm + mt * 16 + rloc;
                uint32_t off = 16u * (ks * 256 + r * 2 + (hsel ^ ((r >> 2) & 1)));
                ldsm4(ah[mt], stg + off);
            }
#pragma unroll
            for (int g = 0; g < 4; ++g) {
                int r = wn + g * 16 + rloc;
                uint32_t off = 16u * (ks * 256 + r * 2 + (hsel ^ ((r >> 2) & 1)));
                uint32_t bh[4];
                ldsm4(bh, stg + 8192 + off);
                uint32_t b0h[2] = {bh[0], bh[2]}, b1h[2] = {bh[1], bh[3]};
#pragma unroll
                for (int mt = 0; mt < 2; ++mt) {
                    mma_f16(acc[mt][2 * g],     ah[mt], b0h);
                    mma_f16(acc[mt][2 * g + 1], ah[mt], b1h);
                }
            }
        }
        __syncthreads();
    }
#undef ISSUE

    /* ---- epilogue ---- */
#pragma unroll
    for (int mt = 0; mt < 2; ++mt) {
#pragma unroll
        for (int f = 0; f < 8; ++f) {
            const int n = n0 + wn + (f >> 1) * 16 + (f & 1) * 8 + (lane & 3) * 2;
            const float2 bv = *(const float2*)&bias[n];
#pragma unroll
            for (int hrow = 0; hrow < 2; ++hrow) {
                const int m = m0 + wm + mt * 16 + (lane >> 2) + hrow * 8;
                float vx = acc[mt][f][hrow * 2 + 0] + bv.x;
                float vy = acc[mt][f][hrow * 2 + 1] + bv.y;
                if (MODE == 0) {
                    const int sel = n >> 9;
                    const int h = (n >> 5) & 15, d = n & 31;
                    if (sel == 0) { vx *= SCALE_F; vy *= SCALE_F; }
                    __half* dst = (sel == 0) ? g_q : ((sel == 1) ? g_k : g_v);
                    size_t base = (((size_t)(m >> 6) * NH + h) * NTOK + (m & 63)) * HD + d;
                    *(uint32_t*)&dst[base] = pack_h2(vx, vy);
                } else {
                    *(float2*)&out[(size_t)m * DIMC + n] = make_float2(vx, vy);
                }
            }
        }
    }
}

/* ================= tensor-core attention (fp16 single-term) ============== */
/* CTA = (b, head-pair). 8 warps: warp -> (head = 2*hp + w/4, mtile = w%4). */
#define VROWB 80   /* padded v smem row bytes (32 fp16 = 64B + 16B pad) */

__global__ __launch_bounds__(256, 2) void attn_mma_kernel()
{
    const int cta = blockIdx.x;           /* 0 .. 8191 */
    const int b = cta >> 3, hp = cta & 7;
    const int tid = threadIdx.x, wid = tid >> 5, lane = tid & 31;
    const int h2 = wid >> 2;
    const int h  = hp * 2 + h2;
    const int m0 = (wid & 3) << 4;

    __shared__ __align__(16) unsigned char vbuf[2][64 * VROWB];

    /* stage v for both heads: [tok][d] rows padded to 80B */
    {
        const size_t vb0 = ((size_t)b * NH + hp * 2) * (NTOK * HD);
        const uint32_t* sv = (const uint32_t*)g_v + vb0 / 2;
        for (int e = tid; e < 2048; e += 256) {        /* 2 heads x 1024 u32 */
            int hh = e >> 10, e2 = e & 1023;
            int row = e2 >> 4, c = e2 & 15;
            *(uint32_t*)&vbuf[hh][row * VROWB + c * 4] = sv[hh * 1024 + row * 16 + c];
        }
    }
    __syncthreads();

    const size_t qkb = ((size_t)b * NH + h) * (NTOK * HD);
    const __half* qh = g_q + qkb;
    const __half* kh = g_k + qkb;

    const int rA = m0 + (lane >> 2);      /* local token row */
    const int cp = (lane & 3) << 1;       /* fragment col pair */

    /* q fragments (A operand), 2 k-tiles of 16 over d=32 */
    uint32_t aq[2][4];
#pragma unroll
    for (int kt = 0; kt < 2; ++kt) {
        const int kc = kt * 16 + cp;
        aq[kt][0] = *(const uint32_t*)&qh[(size_t)rA * HD + kc];
        aq[kt][1] = *(const uint32_t*)&qh[(size_t)(rA + 8) * HD + kc];
        aq[kt][2] = *(const uint32_t*)&qh[(size_t)rA * HD + kc + 8];
        aq[kt][3] = *(const uint32_t*)&qh[(size_t)(rA + 8) * HD + kc + 8];
    }

    /* S = q k^T, 8 n-tiles of 8 cols */
    float sc[8][4];
#pragma unroll
    for (int nt = 0; nt < 8; ++nt) { sc[nt][0] = sc[nt][1] = sc[nt][2] = sc[nt][3] = 0.0f; }
    const int nrow = (lane >> 2);
#pragma unroll
    for (int nt = 0; nt < 8; ++nt) {
        const size_t krow = (size_t)(nt * 8 + nrow) * HD;
#pragma unroll
        for (int kt = 0; kt < 2; ++kt) {
            const int kc = kt * 16 + cp;
            uint32_t bh[2];
            bh[0] = *(const uint32_t*)&kh[krow + kc];
            bh[1] = *(const uint32_t*)&kh[krow + kc + 8];
            mma_f16(sc[nt], aq[kt], bh);
        }
    }

    /* + bias */
    const float* bp = g_bias + (h << 12);
#pragma unroll
    for (int nt = 0; nt < 8; ++nt) {
        float2 bA = *(const float2*)&bp[rA * 64 + nt * 8 + cp];
        float2 bB = *(const float2*)&bp[(rA + 8) * 64 + nt * 8 + cp];
        sc[nt][0] += bA.x; sc[nt][1] += bA.y;
        sc[nt][2] += bB.x; sc[nt][3] += bB.y;
    }

    /* softmax (rows rA and rA+8), 4-lane groups */
    float mA = -1e30f, mB = -1e30f;
#pragma unroll
    for (int nt = 0; nt < 8; ++nt) {
        mA = fmaxf(mA, fmaxf(sc[nt][0], sc[nt][1]));
        mB = fmaxf(mB, fmaxf(sc[nt][2], sc[nt][3]));
    }
    mA = fmaxf(mA, __shfl_xor_sync(0xffffffffu, mA, 1));
    mA = fmaxf(mA, __shfl_xor_sync(0xffffffffu, mA, 2));
    mB = fmaxf(mB, __shfl_xor_sync(0xffffffffu, mB, 1));
    mB = fmaxf(mB, __shfl_xor_sync(0xffffffffu, mB, 2));
    float sA = 0.0f, sB = 0.0f;
#pragma unroll
    for (int nt = 0; nt < 8; ++nt) {
        sc[nt][0] = __expf(sc[nt][0] - mA); sA += sc[nt][0];
        sc[nt][1] = __expf(sc[nt][1] - mA); sA += sc[nt][1];
        sc[nt][2] = __expf(sc[nt][2] - mB); sB += sc[nt][2];
        sc[nt][3] = __expf(sc[nt][3] - mB); sB += sc[nt][3];
    }
    sA += __shfl_xor_sync(0xffffffffu, sA, 1);
    sA += __shfl_xor_sync(0xffffffffu, sA, 2);
    sB += __shfl_xor_sync(0xffffffffu, sB, 1);
    sB += __shfl_xor_sync(0xffffffffu, sB, 2);
    const float iA = 1.0f / sA, iB = 1.0f / sB;
#pragma unroll
    for (int nt = 0; nt < 8; ++nt) {
        sc[nt][0] *= iA; sc[nt][1] *= iA;
        sc[nt][2] *= iB; sc[nt][3] *= iB;
    }

    /* O = P V : P (16x64) from registers, V via ldmatrix.trans */
    float oc[4][4];
#pragma unroll
    for (int nt = 0; nt < 4; ++nt) { oc[nt][0] = oc[nt][1] = oc[nt][2] = oc[nt][3] = 0.0f; }
    const uint32_t v_base = smem_u32(&vbuf[h2][0]);
    const uint32_t lrow = (lane & 7) + ((lane >> 3) & 1) * 8;
    const uint32_t lcol16 = (lane >> 4);    /* 0/1 */
#pragma unroll
    for (int kt = 0; kt < 4; ++kt) {
        uint32_t pa[4];
#pragma unroll
        for (int half = 0; half < 2; ++half) {
            const int nt = 2 * kt + half;
            pa[half * 2 + 0] = pack_h2(sc[nt][0], sc[nt][1]);
            pa[half * 2 + 1] = pack_h2(sc[nt][2], sc[nt][3]);
        }
        uint32_t v0[4], v1[4];
        const uint32_t roff = (uint32_t)((kt * 16 + lrow) * VROWB);
        ldsm4t(v0, v_base + roff + lcol16 * 16);
        ldsm4t(v1, v_base + roff + (lcol16 + 2) * 16);
        uint32_t bv[4][2] = {{v0[0], v0[1]}, {v0[2], v0[3]},
                             {v1[0], v1[1]}, {v1[2], v1[3]}};
#pragma unroll
        for (int nt = 0; nt < 4; ++nt)
            mma_f16(oc[nt], pa, bv[nt]);
    }

    /* epilogue: O -> fp16 g_att [b*64+tok][h*32+d] */
    const size_t obA = ((size_t)(b * NTOK + rA)) * DIMC + h * HD;
    const size_t obB = obA + (size_t)8 * DIMC;
#pragma unroll
    for (int nt = 0; nt < 4; ++nt) {
        const int d = nt * 8 + cp;
        *(uint32_t*)&g_att[obA + d] = pack_h2(oc[nt][0], oc[nt][1]);
        *(uint32_t*)&g_att[obB + d] = pack_h2(oc[nt][2], oc[nt][3]);
    }
}

/* ========================================================================= */
extern "C" void kernel_launch(void* const* d_in, const int* in_sizes, int n_in,
                              void* d_out, int out_size)
{
    (void)in_sizes; (void)n_in; (void)out_size;
    const float* x      = (const float*)d_in[0];
    const float* theta  = (const float*)d_in[1];
    const float* qkv_w  = (const float*)d_in[2];
    const float* qkv_b  = (const float*)d_in[3];
    const float* proj_w = (const float*)d_in[4];
    const float* proj_b = (const float*)d_in[5];
    const float* a_p    = (const float*)d_in[6];
    const float* b_p    = (const float*)d_in[7];
    const float* a_r    = (const float*)d_in[8];
    const float* b_r    = (const float*)d_in[9];
    float* out = (float*)d_out;

    static int smem_set = 0;
    if (!smem_set) {
        cudaFuncSetAttribute(mma_gemm<0>, cudaFuncAttributeMaxDynamicSharedMemorySize, SMEM_TOTAL);
        cudaFuncSetAttribute(mma_gemm<1>, cudaFuncAttributeMaxDynamicSharedMemorySize, SMEM_TOTAL);
        smem_set = 1;
    }

    bias_kernel<<<256, 256>>>(theta, a_p, b_p, a_r, b_r);
    cvt_kernel<<<(M_TOT * DIMC / 4 + 255) / 256, 256>>>(x, 0, M_TOT * DIMC / 4);
    cvt_kernel<<<(3 * DIMC * DIMC / 4 + 255) / 256, 256>>>(qkv_w, 1, 3 * DIMC * DIMC / 4);
    cvt_kernel<<<(DIMC * DIMC / 4 + 255) / 256, 256>>>(proj_w, 2, DIMC * DIMC / 4);
    mma_gemm<0><<<dim3(12, 512), 256, SMEM_TOTAL>>>(qkv_b, nullptr);
    attn_mma_kernel<<<B_WIN * 8, 256>>>();
    mma_gemm<1><<<dim3(4, 512), 256, SMEM_TOTAL>>>(proj_b, out);
}

// round 8
// speedup vs baseline: 4.7160x; 1.1335x over previous
#include <cuda_runtime.h>
#include <cuda_fp16.h>
#include <stdint.h>
#include <math.h>

#define B_WIN   1024
#define NTOK    64
#define DIMC    512
#define NH      16
#define HD      32
#define M_TOT   (B_WIN * NTOK)           /* 65536 */
#define SCALE_F 0.17677669529663687f     /* 32^-0.5 */

/* ---------------- static device scratch (no allocation) ------------------ */
__device__ float g_bias[NH * NTOK * NTOK];
__device__ __half g_x[(size_t)M_TOT * DIMC];
__device__ __half g_att[(size_t)M_TOT * DIMC];     /* [b*64+tok][h*32+d] */
__device__ __half g_wq[3 * DIMC * DIMC];
__device__ __half g_wp[DIMC * DIMC];
/* q/k/v fp16, layout [b][h][tok][d] */
__device__ __half g_q[(size_t)M_TOT * DIMC];
__device__ __half g_k[(size_t)M_TOT * DIMC];
__device__ __half g_v[(size_t)M_TOT * DIMC];

/* ---------------- portable tensor-core helpers (sm_80+) ------------------ */
__device__ __forceinline__ uint32_t smem_u32(const void* p) {
    return (uint32_t)__cvta_generic_to_shared(p);
}
__device__ __forceinline__ void ldsm4(uint32_t* r, uint32_t addr) {
    asm volatile("ldmatrix.sync.aligned.m8n8.x4.shared.b16 {%0,%1,%2,%3}, [%4];"
        : "=r"(r[0]), "=r"(r[1]), "=r"(r[2]), "=r"(r[3]) : "r"(addr));
}
__device__ __forceinline__ void ldsm4t(uint32_t* r, uint32_t addr) {
    asm volatile("ldmatrix.sync.aligned.m8n8.x4.trans.shared.b16 {%0,%1,%2,%3}, [%4];"
        : "=r"(r[0]), "=r"(r[1]), "=r"(r[2]), "=r"(r[3]) : "r"(addr));
}
__device__ __forceinline__ void mma_f16(float* d, const uint32_t* a, const uint32_t* b) {
    asm volatile("mma.sync.aligned.m16n8k16.row.col.f32.f16.f16.f32 "
        "{%0,%1,%2,%3}, {%4,%5,%6,%7}, {%8,%9}, {%0,%1,%2,%3};"
        : "+f"(d[0]), "+f"(d[1]), "+f"(d[2]), "+f"(d[3])
        : "r"(a[0]), "r"(a[1]), "r"(a[2]), "r"(a[3]), "r"(b[0]), "r"(b[1]));
}
#define CP_ASYNC16(dst, src) \
    asm volatile("cp.async.cg.shared.global [%0], [%1], 16;" :: "r"(dst), "l"(src))
#define CP_COMMIT()  asm volatile("cp.async.commit_group;" ::: "memory")
#define CP_WAIT1()   asm volatile("cp.async.wait_group 1;" ::: "memory")
#define CP_WAIT0()   asm volatile("cp.async.wait_group 0;" ::: "memory")

__device__ __forceinline__ uint32_t pack_h2(float a, float b) {
    __half2 h = __floats2half2_rn(a, b);
    return *(uint32_t*)&h;
}
__device__ __forceinline__ uint32_t ex2_h2(uint32_t t) {
    uint32_t r;
    asm("ex2.approx.f16x2 %0, %1;" : "=r"(r) : "r"(t));
    return r;
}

/* ================= bias table ============================================ */
__global__ void bias_kernel(const float* __restrict__ theta_max,
                            const float* __restrict__ a_p, const float* __restrict__ b_p,
                            const float* __restrict__ a_r, const float* __restrict__ b_r)
{
    int idx = blockIdx.x * 256 + threadIdx.x;
    int h = idx >> 12;
    int ij = idx & 4095;
    int i = ij >> 6, j = ij & 63;
    int dr = (i >> 3) - (j >> 3);
    int dc = (i & 7) - (j & 7);
    int idx_r  = ((dr % 15) + 15) % 15;
    int idx_az = ((dc % 15) + 15) % 15;
    float az = (float)dc * (2.0f * 3.14159265358979323846f / 32.0f);
    float ra = (float)dr * (theta_max[0] / 32.0f);
    g_bias[idx] = a_p[idx_az * NH + h] * cosf(az) + b_p[idx_az * NH + h] * sinf(az)
                + a_r[idx_r  * NH + h] * cosf(ra) + b_r[idx_r  * NH + h] * sinf(ra);
}

/* ================= fp32 -> fp16 convert ================================== */
__global__ void cvt_kernel(const float* __restrict__ src, int which, int n4)
{
    int i = blockIdx.x * 256 + threadIdx.x;
    if (i >= n4) return;
    float4 v = ((const float4*)src)[i];
    uint2 H = make_uint2(pack_h2(v.x, v.y), pack_h2(v.z, v.w));
    __half* hp = (which == 0) ? g_x : ((which == 1) ? g_wq : g_wp);
    ((uint2*)hp)[i] = H;
}

/* ================= mma.sync fp16 GEMM ==================================== */
#define STAGE_B 16384
#define SMEM_TOTAL (2 * STAGE_B)

template<int MODE>
__global__ __launch_bounds__(256, 2) void mma_gemm(const float* __restrict__ bias,
                                                   float* __restrict__ out)
{
    extern __shared__ char smem[];
    const uint32_t sb = smem_u32(smem);
    const int tid = threadIdx.x, wid = tid >> 5, lane = tid & 31;
    const int m0 = blockIdx.y << 7;
    const int n0 = blockIdx.x << 7;
    const int wm = (wid & 3) << 5;
    const int wn = (wid >> 2) << 6;

    const __half* __restrict__ A = (MODE == 0) ? g_x : g_att;
    const __half* __restrict__ W = (MODE == 0) ? g_wq : g_wp;

    float acc[2][8][4];
#pragma unroll
    for (int a = 0; a < 2; a++)
#pragma unroll
        for (int b = 0; b < 8; b++)
#pragma unroll
            for (int c = 0; c < 4; c++) acc[a][b][c] = 0.0f;

    const int c_r0   = tid >> 2,          c_q0 = tid & 3;
    const int c_r1   = (tid + 256) >> 2;
    const int ksl0 = c_q0 >> 1, half0 = c_q0 & 1;
    const uint32_t off0 = 16u * (ksl0 * 256 + c_r0 * 2 + (half0 ^ ((c_r0 >> 2) & 1)));
    const uint32_t off1 = 16u * (ksl0 * 256 + c_r1 * 2 + (half0 ^ ((c_r1 >> 2) & 1)));
    const int kc0 = ksl0 * 16 + half0 * 8;

#define ISSUE(ch) do {                                                         \
    const uint32_t stg = sb + ((ch) & 1) * STAGE_B;                            \
    const int kk = ((ch) << 5) + kc0;                                          \
    size_t a0 = (size_t)(m0 + c_r0) * DIMC + kk;                               \
    size_t a1 = (size_t)(m0 + c_r1) * DIMC + kk;                               \
    size_t b0 = (size_t)(n0 + c_r0) * DIMC + kk;                               \
    size_t b1 = (size_t)(n0 + c_r1) * DIMC + kk;                               \
    CP_ASYNC16(stg + off0,        A + a0);                                     \
    CP_ASYNC16(stg + off1,        A + a1);                                     \
    CP_ASYNC16(stg + 8192 + off0, W + b0);                                     \
    CP_ASYNC16(stg + 8192 + off1, W + b1);                                     \
    CP_COMMIT();                                                               \
} while (0)

    ISSUE(0);
    const int rloc = lane & 15, hsel = lane >> 4;
    for (int ch = 0; ch < 16; ++ch) {
        if (ch < 15) { ISSUE(ch + 1); CP_WAIT1(); }
        else         { CP_WAIT0(); }
        __syncthreads();
        const uint32_t stg = sb + (ch & 1) * STAGE_B;
#pragma unroll
        for (int ks = 0; ks < 2; ++ks) {
            uint32_t ah[2][4];
#pragma unroll
            for (int mt = 0; mt < 2; ++mt) {
                int r = wm + mt * 16 + rloc;
                uint32_t off = 16u * (ks * 256 + r * 2 + (hsel ^ ((r >> 2) & 1)));
                ldsm4(ah[mt], stg + off);
            }
#pragma unroll
            for (int g = 0; g < 4; ++g) {
                int r = wn + g * 16 + rloc;
                uint32_t off = 16u * (ks * 256 + r * 2 + (hsel ^ ((r >> 2) & 1)));
                uint32_t bh[4];
                ldsm4(bh, stg + 8192 + off);
                uint32_t b0h[2] = {bh[0], bh[2]}, b1h[2] = {bh[1], bh[3]};
#pragma unroll
                for (int mt = 0; mt < 2; ++mt) {
                    mma_f16(acc[mt][2 * g],     ah[mt], b0h);
                    mma_f16(acc[mt][2 * g + 1], ah[mt], b1h);
                }
            }
        }
        __syncthreads();
    }
#undef ISSUE

    /* ---- epilogue ---- */
#pragma unroll
    for (int mt = 0; mt < 2; ++mt) {
#pragma unroll
        for (int f = 0; f < 8; ++f) {
            const int n = n0 + wn + (f >> 1) * 16 + (f & 1) * 8 + (lane & 3) * 2;
            const float2 bv = *(const float2*)&bias[n];
#pragma unroll
            for (int hrow = 0; hrow < 2; ++hrow) {
                const int m = m0 + wm + mt * 16 + (lane >> 2) + hrow * 8;
                float vx = acc[mt][f][hrow * 2 + 0] + bv.x;
                float vy = acc[mt][f][hrow * 2 + 1] + bv.y;
                if (MODE == 0) {
                    const int sel = n >> 9;
                    const int h = (n >> 5) & 15, d = n & 31;
                    if (sel == 0) { vx *= SCALE_F; vy *= SCALE_F; }
                    __half* dst = (sel == 0) ? g_q : ((sel == 1) ? g_k : g_v);
                    size_t base = (((size_t)(m >> 6) * NH + h) * NTOK + (m & 63)) * HD + d;
                    *(uint32_t*)&dst[base] = pack_h2(vx, vy);
                } else {
                    *(float2*)&out[(size_t)m * DIMC + n] = make_float2(vx, vy);
                }
            }
        }
    }
}

/* ================= tensor-core attention (fp16, f16x2 exp) =============== */
/* CTA = (b, head-pair). 8 warps: warp -> (head = 2*hp + w/4, mtile = w%4). */
/* q/k/v staged via cp.async into 80B-pitch smem; frags via ldmatrix.       */
#define PITCH 80

__global__ __launch_bounds__(256, 2) void attn_mma_kernel()
{
    const int cta = blockIdx.x;           /* 0 .. 8191 */
    const int b = cta >> 3, hp = cta & 7;
    const int tid = threadIdx.x, wid = tid >> 5, lane = tid & 31;
    const int h2 = wid >> 2;
    const int h  = hp * 2 + h2;
    const int m0 = (wid & 3) << 4;

    __shared__ __align__(16) unsigned char qbuf[2][64 * PITCH];
    __shared__ __align__(16) unsigned char kbuf[2][64 * PITCH];
    __shared__ __align__(16) unsigned char vbuf[2][64 * PITCH];

    /* stage q,k,v for both heads: 1536 x 16B chunks, 6 per thread */
    {
        const size_t base0 = ((size_t)b * NH + hp * 2) * (NTOK * HD);
#pragma unroll
        for (int it = 0; it < 6; ++it) {
            int e = tid + it * 256;
            int which = e / 512;
            int e2 = e & 511;
            int hh = e2 >> 8;
            int e3 = e2 & 255;
            int r = e3 >> 2, c = e3 & 3;
            const __half* gsrc = (which == 0) ? g_q : ((which == 1) ? g_k : g_v);
            unsigned char* dbuf = (which == 0) ? &qbuf[hh][0]
                                : ((which == 1) ? &kbuf[hh][0] : &vbuf[hh][0]);
            CP_ASYNC16(smem_u32(dbuf + r * PITCH + c * 16),
                       gsrc + base0 + (size_t)hh * (NTOK * HD) + r * HD + c * 8);
        }
        CP_COMMIT();
        CP_WAIT0();
    }
    __syncthreads();

    const uint32_t qb = smem_u32(&qbuf[h2][0]);
    const uint32_t kb = smem_u32(&kbuf[h2][0]);
    const uint32_t vb = smem_u32(&vbuf[h2][0]);

    const int rA = m0 + (lane >> 2);      /* local token row (frag row) */
    const int cp = (lane & 3) << 1;       /* fragment col pair */

    /* q A-frags via ldsm4: rows m0..m0+15, 2 k-tiles over d=32 */
    uint32_t aq[2][4];
    {
        const int arow = m0 + (lane & 7) + ((lane >> 3) & 1) * 8;
        const uint32_t acol = (lane >> 4) * 16;
#pragma unroll
        for (int kt = 0; kt < 2; ++kt)
            ldsm4(aq[kt], qb + (uint32_t)arow * PITCH + kt * 32 + acol);
    }

    /* S = q k^T: B-frags from kbuf rows (tokens) */
    float sc[8][4];
#pragma unroll
    for (int nt = 0; nt < 8; ++nt) { sc[nt][0] = sc[nt][1] = sc[nt][2] = sc[nt][3] = 0.0f; }
    {
        const int brow_l = lane & 15;
        const uint32_t bcol = (lane >> 4) * 16;
#pragma unroll
        for (int g = 0; g < 4; ++g) {
            const uint32_t roff = (uint32_t)(g * 16 + brow_l) * PITCH;
#pragma unroll
            for (int kt = 0; kt < 2; ++kt) {
                uint32_t bt[4];
                ldsm4(bt, kb + roff + kt * 32 + bcol);
                uint32_t b0[2] = {bt[0], bt[2]}, b1[2] = {bt[1], bt[3]};
                mma_f16(sc[2 * g],     aq[kt], b0);
                mma_f16(sc[2 * g + 1], aq[kt], b1);
            }
        }
    }

    /* + bias */
    const float* bp = g_bias + (h << 12);
#pragma unroll
    for (int nt = 0; nt < 8; ++nt) {
        float2 bA = *(const float2*)&bp[rA * 64 + nt * 8 + cp];
        float2 bB = *(const float2*)&bp[(rA + 8) * 64 + nt * 8 + cp];
        sc[nt][0] += bA.x; sc[nt][1] += bA.y;
        sc[nt][2] += bB.x; sc[nt][3] += bB.y;
    }

    /* softmax: max-reduce, exp via ex2.approx.f16x2, deferred normalization */
    float mA = -1e30f, mB = -1e30f;
#pragma unroll
    for (int nt = 0; nt < 8; ++nt) {
        mA = fmaxf(mA, fmaxf(sc[nt][0], sc[nt][1]));
        mB = fmaxf(mB, fmaxf(sc[nt][2], sc[nt][3]));
    }
    mA = fmaxf(mA, __shfl_xor_sync(0xffffffffu, mA, 1));
    mA = fmaxf(mA, __shfl_xor_sync(0xffffffffu, mA, 2));
    mB = fmaxf(mB, __shfl_xor_sync(0xffffffffu, mB, 1));
    mB = fmaxf(mB, __shfl_xor_sync(0xffffffffu, mB, 2));

    const float L2E = 1.4426950408889634f;
    uint32_t pe[8][2];                       /* P fp16x2: [nt][rowA/rowB] */
    float sA = 0.0f, sB = 0.0f;
#pragma unroll
    for (int nt = 0; nt < 8; ++nt) {
        uint32_t uA = pack_h2((sc[nt][0] - mA) * L2E, (sc[nt][1] - mA) * L2E);
        uint32_t uB = pack_h2((sc[nt][2] - mB) * L2E, (sc[nt][3] - mB) * L2E);
        pe[nt][0] = ex2_h2(uA);
        pe[nt][1] = ex2_h2(uB);
        float2 fA = __half22float2(*(__half2*)&pe[nt][0]);
        float2 fB = __half22float2(*(__half2*)&pe[nt][1]);
        sA += fA.x + fA.y;
        sB += fB.x + fB.y;
    }
    sA += __shfl_xor_sync(0xffffffffu, sA, 1);
    sA += __shfl_xor_sync(0xffffffffu, sA, 2);
    sB += __shfl_xor_sync(0xffffffffu, sB, 1);
    sB += __shfl_xor_sync(0xffffffffu, sB, 2);
    const float iA = 1.0f / sA, iB = 1.0f / sB;

    /* O = P V (unnormalized), V via ldmatrix.trans from vbuf */
    float oc[4][4];
#pragma unroll
    for (int nt = 0; nt < 4; ++nt) { oc[nt][0] = oc[nt][1] = oc[nt][2] = oc[nt][3] = 0.0f; }
    const uint32_t lrow = (lane & 7) + ((lane >> 3) & 1) * 8;
    const uint32_t lcol16 = (lane >> 4);
#pragma unroll
    for (int kt = 0; kt < 4; ++kt) {
        uint32_t pa[4] = {pe[2 * kt][0], pe[2 * kt][1],
                          pe[2 * kt + 1][0], pe[2 * kt + 1][1]};
        uint32_t v0[4], v1[4];
        const uint32_t roff = (uint32_t)((kt * 16 + lrow) * PITCH);
        ldsm4t(v0, vb + roff + lcol16 * 16);
        ldsm4t(v1, vb + roff + (lcol16 + 2) * 16);
        uint32_t bv[4][2] = {{v0[0], v0[1]}, {v0[2], v0[3]},
                             {v1[0], v1[1]}, {v1[2], v1[3]}};
#pragma unroll
        for (int nt = 0; nt < 4; ++nt)
            mma_f16(oc[nt], pa, bv[nt]);
    }

    /* epilogue: normalize rows and write fp16 to g_att */
    const size_t obA = ((size_t)(b * NTOK + rA)) * DIMC + h * HD;
    const size_t obB = obA + (size_t)8 * DIMC;
#pragma unroll
    for (int nt = 0; nt < 4; ++nt) {
        const int d = nt * 8 + cp;
        *(uint32_t*)&g_att[obA + d] = pack_h2(oc[nt][0] * iA, oc[nt][1] * iA);
        *(uint32_t*)&g_att[obB + d] = pack_h2(oc[nt][2] * iB, oc[nt][3] * iB);
    }
}

/* ========================================================================= */
extern "C" void kernel_launch(void* const* d_in, const int* in_sizes, int n_in,
                              void* d_out, int out_size)
{
    (void)in_sizes; (void)n_in; (void)out_size;
    const float* x      = (const float*)d_in[0];
    const float* theta  = (const float*)d_in[1];
    const float* qkv_w  = (const float*)d_in[2];
    const float* qkv_b  = (const float*)d_in[3];
    const float* proj_w = (const float*)d_in[4];
    const float* proj_b = (const float*)d_in[5];
    const float* a_p    = (const float*)d_in[6];
    const float* b_p    = (const float*)d_in[7];
    const float* a_r    = (const float*)d_in[8];
    const float* b_r    = (const float*)d_in[9];
    float* out = (float*)d_out;

    static int smem_set = 0;
    if (!smem_set) {
        cudaFuncSetAttribute(mma_gemm<0>, cudaFuncAttributeMaxDynamicSharedMemorySize, SMEM_TOTAL);
        cudaFuncSetAttribute(mma_gemm<1>, cudaFuncAttributeMaxDynamicSharedMemorySize, SMEM_TOTAL);
        smem_set = 1;
    }

    bias_kernel<<<256, 256>>>(theta, a_p, b_p, a_r, b_r);
    cvt_kernel<<<(M_TOT * DIMC / 4 + 255) / 256, 256>>>(x, 0, M_TOT * DIMC / 4);
    cvt_kernel<<<(3 * DIMC * DIMC / 4 + 255) / 256, 256>>>(qkv_w, 1, 3 * DIMC * DIMC / 4);
    cvt_kernel<<<(DIMC * DIMC / 4 + 255) / 256, 256>>>(proj_w, 2, DIMC * DIMC / 4);
    mma_gemm<0><<<dim3(12, 512), 256, SMEM_TOTAL>>>(qkv_b, nullptr);
    attn_mma_kernel<<<B_WIN * 8, 256>>>();
    mma_gemm<1><<<dim3(4, 512), 256, SMEM_TOTAL>>>(proj_b, out);
}

// round 9
// speedup vs baseline: 4.8014x; 1.0181x over previous
#include <cuda_runtime.h>
#include <cuda_fp16.h>
#include <stdint.h>
#include <math.h>

#define B_WIN   1024
#define NTOK    64
#define DIMC    512
#define NH      16
#define HD      32
#define M_TOT   (B_WIN * NTOK)           /* 65536 */
#define SCALE_F 0.17677669529663687f     /* 32^-0.5 */

/* ---------------- static device scratch (no allocation) ------------------ */
__device__ float g_bias[NH * NTOK * NTOK];
__device__ __half g_x[(size_t)M_TOT * DIMC];
__device__ __half g_att[(size_t)M_TOT * DIMC];     /* [b*64+tok][h*32+d] */
__device__ __half g_wq[3 * DIMC * DIMC];
__device__ __half g_wp[DIMC * DIMC];
/* q/k/v fp16, layout [b][h][tok][d] */
__device__ __half g_q[(size_t)M_TOT * DIMC];
__device__ __half g_k[(size_t)M_TOT * DIMC];
__device__ __half g_v[(size_t)M_TOT * DIMC];

/* ---------------- portable tensor-core helpers (sm_80+) ------------------ */
__device__ __forceinline__ uint32_t smem_u32(const void* p) {
    return (uint32_t)__cvta_generic_to_shared(p);
}
__device__ __forceinline__ void ldsm4(uint32_t* r, uint32_t addr) {
    asm volatile("ldmatrix.sync.aligned.m8n8.x4.shared.b16 {%0,%1,%2,%3}, [%4];"
        : "=r"(r[0]), "=r"(r[1]), "=r"(r[2]), "=r"(r[3]) : "r"(addr));
}
__device__ __forceinline__ void ldsm4t(uint32_t* r, uint32_t addr) {
    asm volatile("ldmatrix.sync.aligned.m8n8.x4.trans.shared.b16 {%0,%1,%2,%3}, [%4];"
        : "=r"(r[0]), "=r"(r[1]), "=r"(r[2]), "=r"(r[3]) : "r"(addr));
}
__device__ __forceinline__ void mma_f16(float* d, const uint32_t* a, const uint32_t* b) {
    asm volatile("mma.sync.aligned.m16n8k16.row.col.f32.f16.f16.f32 "
        "{%0,%1,%2,%3}, {%4,%5,%6,%7}, {%8,%9}, {%0,%1,%2,%3};"
        : "+f"(d[0]), "+f"(d[1]), "+f"(d[2]), "+f"(d[3])
        : "r"(a[0]), "r"(a[1]), "r"(a[2]), "r"(a[3]), "r"(b[0]), "r"(b[1]));
}
#define CP_ASYNC16(dst, src) \
    asm volatile("cp.async.cg.shared.global [%0], [%1], 16;" :: "r"(dst), "l"(src))
#define CP_COMMIT()  asm volatile("cp.async.commit_group;" ::: "memory")
#define CP_WAIT2()   asm volatile("cp.async.wait_group 2;" ::: "memory")
#define CP_WAIT1()   asm volatile("cp.async.wait_group 1;" ::: "memory")
#define CP_WAIT0()   asm volatile("cp.async.wait_group 0;" ::: "memory")

__device__ __forceinline__ uint32_t pack_h2(float a, float b) {
    __half2 h = __floats2half2_rn(a, b);
    return *(uint32_t*)&h;
}
__device__ __forceinline__ uint32_t ex2_h2(uint32_t t) {
    uint32_t r;
    asm("ex2.approx.f16x2 %0, %1;" : "=r"(r) : "r"(t));
    return r;
}

/* ================= bias table ============================================ */
__global__ void bias_kernel(const float* __restrict__ theta_max,
                            const float* __restrict__ a_p, const float* __restrict__ b_p,
                            const float* __restrict__ a_r, const float* __restrict__ b_r)
{
    int idx = blockIdx.x * 256 + threadIdx.x;
    int h = idx >> 12;
    int ij = idx & 4095;
    int i = ij >> 6, j = ij & 63;
    int dr = (i >> 3) - (j >> 3);
    int dc = (i & 7) - (j & 7);
    int idx_r  = ((dr % 15) + 15) % 15;
    int idx_az = ((dc % 15) + 15) % 15;
    float az = (float)dc * (2.0f * 3.14159265358979323846f / 32.0f);
    float ra = (float)dr * (theta_max[0] / 32.0f);
    g_bias[idx] = a_p[idx_az * NH + h] * cosf(az) + b_p[idx_az * NH + h] * sinf(az)
                + a_r[idx_r  * NH + h] * cosf(ra) + b_r[idx_r  * NH + h] * sinf(ra);
}

/* ================= fp32 -> fp16 convert ================================== */
__global__ void cvt_kernel(const float* __restrict__ src, int which, int n4)
{
    int i = blockIdx.x * 256 + threadIdx.x;
    if (i >= n4) return;
    float4 v = ((const float4*)src)[i];
    uint2 H = make_uint2(pack_h2(v.x, v.y), pack_h2(v.z, v.w));
    __half* hp = (which == 0) ? g_x : ((which == 1) ? g_wq : g_wp);
    ((uint2*)hp)[i] = H;
}

/* ================= mma.sync fp16 GEMM (4-stage cp.async ring) ============ */
#define STAGE_B 16384
#define SMEM_TOTAL (4 * STAGE_B)

template<int MODE>
__global__ __launch_bounds__(256, 2) void mma_gemm(const float* __restrict__ bias,
                                                   float* __restrict__ out)
{
    extern __shared__ char smem[];
    const uint32_t sb = smem_u32(smem);
    const int tid = threadIdx.x, wid = tid >> 5, lane = tid & 31;
    const int m0 = blockIdx.y << 7;
    const int n0 = blockIdx.x << 7;
    const int wm = (wid & 3) << 5;
    const int wn = (wid >> 2) << 6;

    const __half* __restrict__ A = (MODE == 0) ? g_x : g_att;
    const __half* __restrict__ W = (MODE == 0) ? g_wq : g_wp;

    float acc[2][8][4];
#pragma unroll
    for (int a = 0; a < 2; a++)
#pragma unroll
        for (int b = 0; b < 8; b++)
#pragma unroll
            for (int c = 0; c < 4; c++) acc[a][b][c] = 0.0f;

    const int c_r0   = tid >> 2,          c_q0 = tid & 3;
    const int c_r1   = (tid + 256) >> 2;
    const int ksl0 = c_q0 >> 1, half0 = c_q0 & 1;
    const uint32_t off0 = 16u * (ksl0 * 256 + c_r0 * 2 + (half0 ^ ((c_r0 >> 2) & 1)));
    const uint32_t off1 = 16u * (ksl0 * 256 + c_r1 * 2 + (half0 ^ ((c_r1 >> 2) & 1)));
    const int kc0 = ksl0 * 16 + half0 * 8;

#define ISSUE(ch) do {                                                         \
    const uint32_t stg = sb + ((ch) & 3) * STAGE_B;                            \
    const int kk = ((ch) << 5) + kc0;                                          \
    size_t a0 = (size_t)(m0 + c_r0) * DIMC + kk;                               \
    size_t a1 = (size_t)(m0 + c_r1) * DIMC + kk;                               \
    size_t b0 = (size_t)(n0 + c_r0) * DIMC + kk;                               \
    size_t b1 = (size_t)(n0 + c_r1) * DIMC + kk;                               \
    CP_ASYNC16(stg + off0,        A + a0);                                     \
    CP_ASYNC16(stg + off1,        A + a1);                                     \
    CP_ASYNC16(stg + 8192 + off0, W + b0);                                     \
    CP_ASYNC16(stg + 8192 + off1, W + b1);                                     \
    CP_COMMIT();                                                               \
} while (0)

    ISSUE(0); ISSUE(1); ISSUE(2);
    const int rloc = lane & 15, hsel = lane >> 4;
    for (int ch = 0; ch < 16; ++ch) {
        /* drain so group ch is complete (tail-aware) */
        if (ch <= 13)      CP_WAIT2();
        else if (ch == 14) CP_WAIT1();
        else               CP_WAIT0();
        __syncthreads();
        if (ch + 3 < 16) ISSUE(ch + 3);
        const uint32_t stg = sb + (ch & 3) * STAGE_B;
#pragma unroll
        for (int ks = 0; ks < 2; ++ks) {
            uint32_t ah[2][4];
#pragma unroll
            for (int mt = 0; mt < 2; ++mt) {
                int r = wm + mt * 16 + rloc;
                uint32_t off = 16u * (ks * 256 + r * 2 + (hsel ^ ((r >> 2) & 1)));
                ldsm4(ah[mt], stg + off);
            }
#pragma unroll
            for (int g = 0; g < 4; ++g) {
                int r = wn + g * 16 + rloc;
                uint32_t off = 16u * (ks * 256 + r * 2 + (hsel ^ ((r >> 2) & 1)));
                uint32_t bh[4];
                ldsm4(bh, stg + 8192 + off);
                uint32_t b0h[2] = {bh[0], bh[2]}, b1h[2] = {bh[1], bh[3]};
#pragma unroll
                for (int mt = 0; mt < 2; ++mt) {
                    mma_f16(acc[mt][2 * g],     ah[mt], b0h);
                    mma_f16(acc[mt][2 * g + 1], ah[mt], b1h);
                }
            }
        }
    }
#undef ISSUE

    /* ---- epilogue ---- */
#pragma unroll
    for (int mt = 0; mt < 2; ++mt) {
#pragma unroll
        for (int f = 0; f < 8; ++f) {
            const int n = n0 + wn + (f >> 1) * 16 + (f & 1) * 8 + (lane & 3) * 2;
            const float2 bv = *(const float2*)&bias[n];
#pragma unroll
            for (int hrow = 0; hrow < 2; ++hrow) {
                const int m = m0 + wm + mt * 16 + (lane >> 2) + hrow * 8;
                float vx = acc[mt][f][hrow * 2 + 0] + bv.x;
                float vy = acc[mt][f][hrow * 2 + 1] + bv.y;
                if (MODE == 0) {
                    const int sel = n >> 9;
                    const int h = (n >> 5) & 15, d = n & 31;
                    if (sel == 0) { vx *= SCALE_F; vy *= SCALE_F; }
                    __half* dst = (sel == 0) ? g_q : ((sel == 1) ? g_k : g_v);
                    size_t base = (((size_t)(m >> 6) * NH + h) * NTOK + (m & 63)) * HD + d;
                    *(uint32_t*)&dst[base] = pack_h2(vx, vy);
                } else {
                    *(float2*)&out[(size_t)m * DIMC + n] = make_float2(vx, vy);
                }
            }
        }
    }
}

/* ================= tensor-core attention (fp16, f16x2 exp, no-max) ====== */
#define PITCH 80

__global__ __launch_bounds__(256, 2) void attn_mma_kernel()
{
    const int cta = blockIdx.x;           /* 0 .. 8191 */
    const int b = cta >> 3, hp = cta & 7;
    const int tid = threadIdx.x, wid = tid >> 5, lane = tid & 31;
    const int h2 = wid >> 2;
    const int h  = hp * 2 + h2;
    const int m0 = (wid & 3) << 4;

    __shared__ __align__(16) unsigned char qbuf[2][64 * PITCH];
    __shared__ __align__(16) unsigned char kbuf[2][64 * PITCH];
    __shared__ __align__(16) unsigned char vbuf[2][64 * PITCH];

    /* stage q,k,v for both heads: 1536 x 16B chunks, 6 per thread */
    {
        const size_t base0 = ((size_t)b * NH + hp * 2) * (NTOK * HD);
#pragma unroll
        for (int it = 0; it < 6; ++it) {
            int e = tid + it * 256;
            int which = e / 512;
            int e2 = e & 511;
            int hh = e2 >> 8;
            int e3 = e2 & 255;
            int r = e3 >> 2, c = e3 & 3;
            const __half* gsrc = (which == 0) ? g_q : ((which == 1) ? g_k : g_v);
            unsigned char* dbuf = (which == 0) ? &qbuf[hh][0]
                                : ((which == 1) ? &kbuf[hh][0] : &vbuf[hh][0]);
            CP_ASYNC16(smem_u32(dbuf + r * PITCH + c * 16),
                       gsrc + base0 + (size_t)hh * (NTOK * HD) + r * HD + c * 8);
        }
        CP_COMMIT();
        CP_WAIT0();
    }
    __syncthreads();

    const uint32_t qb = smem_u32(&qbuf[h2][0]);
    const uint32_t kb = smem_u32(&kbuf[h2][0]);
    const uint32_t vb = smem_u32(&vbuf[h2][0]);

    const int rA = m0 + (lane >> 2);      /* local token row (frag row) */
    const int cp = (lane & 3) << 1;       /* fragment col pair */

    /* q A-frags via ldsm4: rows m0..m0+15, 2 k-tiles over d=32 */
    uint32_t aq[2][4];
    {
        const int arow = m0 + (lane & 7) + ((lane >> 3) & 1) * 8;
        const uint32_t acol = (lane >> 4) * 16;
#pragma unroll
        for (int kt = 0; kt < 2; ++kt)
            ldsm4(aq[kt], qb + (uint32_t)arow * PITCH + kt * 32 + acol);
    }

    /* S = q k^T */
    float sc[8][4];
#pragma unroll
    for (int nt = 0; nt < 8; ++nt) { sc[nt][0] = sc[nt][1] = sc[nt][2] = sc[nt][3] = 0.0f; }
    {
        const int brow_l = lane & 15;
        const uint32_t bcol = (lane >> 4) * 16;
#pragma unroll
        for (int g = 0; g < 4; ++g) {
            const uint32_t roff = (uint32_t)(g * 16 + brow_l) * PITCH;
#pragma unroll
            for (int kt = 0; kt < 2; ++kt) {
                uint32_t bt[4];
                ldsm4(bt, kb + roff + kt * 32 + bcol);
                uint32_t b0[2] = {bt[0], bt[2]}, b1[2] = {bt[1], bt[3]};
                mma_f16(sc[2 * g],     aq[kt], b0);
                mma_f16(sc[2 * g + 1], aq[kt], b1);
            }
        }
    }

    /* + bias */
    const float* bp = g_bias + (h << 12);
#pragma unroll
    for (int nt = 0; nt < 8; ++nt) {
        float2 bA = *(const float2*)&bp[rA * 64 + nt * 8 + cp];
        float2 bB = *(const float2*)&bp[(rA + 8) * 64 + nt * 8 + cp];
        sc[nt][0] += bA.x; sc[nt][1] += bA.y;
        sc[nt][2] += bB.x; sc[nt][3] += bB.y;
    }

    /* softmax without max-subtraction (|S| << fp16 range), deferred norm */
    const float L2E = 1.4426950408889634f;
    uint32_t pe[8][2];                       /* P fp16x2: [nt][rowA/rowB] */
    float sA = 0.0f, sB = 0.0f;
#pragma unroll
    for (int nt = 0; nt < 8; ++nt) {
        uint32_t uA = pack_h2(sc[nt][0] * L2E, sc[nt][1] * L2E);
        uint32_t uB = pack_h2(sc[nt][2] * L2E, sc[nt][3] * L2E);
        pe[nt][0] = ex2_h2(uA);
        pe[nt][1] = ex2_h2(uB);
        float2 fA = __half22float2(*(__half2*)&pe[nt][0]);
        float2 fB = __half22float2(*(__half2*)&pe[nt][1]);
        sA += fA.x + fA.y;
        sB += fB.x + fB.y;
    }
    sA += __shfl_xor_sync(0xffffffffu, sA, 1);
    sA += __shfl_xor_sync(0xffffffffu, sA, 2);
    sB += __shfl_xor_sync(0xffffffffu, sB, 1);
    sB += __shfl_xor_sync(0xffffffffu, sB, 2);
    const float iA = 1.0f / sA, iB = 1.0f / sB;

    /* O = P V (unnormalized), V via ldmatrix.trans */
    float oc[4][4];
#pragma unroll
    for (int nt = 0; nt < 4; ++nt) { oc[nt][0] = oc[nt][1] = oc[nt][2] = oc[nt][3] = 0.0f; }
    const uint32_t lrow = (lane & 7) + ((lane >> 3) & 1) * 8;
    const uint32_t lcol16 = (lane >> 4);
#pragma unroll
    for (int kt = 0; kt < 4; ++kt) {
        uint32_t pa[4] = {pe[2 * kt][0], pe[2 * kt][1],
                          pe[2 * kt + 1][0], pe[2 * kt + 1][1]};
        uint32_t v0[4], v1[4];
        const uint32_t roff = (uint32_t)((kt * 16 + lrow) * PITCH);
        ldsm4t(v0, vb + roff + lcol16 * 16);
        ldsm4t(v1, vb + roff + (lcol16 + 2) * 16);
        uint32_t bv[4][2] = {{v0[0], v0[1]}, {v0[2], v0[3]},
                             {v1[0], v1[1]}, {v1[2], v1[3]}};
#pragma unroll
        for (int nt = 0; nt < 4; ++nt)
            mma_f16(oc[nt], pa, bv[nt]);
    }

    /* epilogue: normalize rows and write fp16 to g_att */
    const size_t obA = ((size_t)(b * NTOK + rA)) * DIMC + h * HD;
    const size_t obB = obA + (size_t)8 * DIMC;
#pragma unroll
    for (int nt = 0; nt < 4; ++nt) {
        const int d = nt * 8 + cp;
        *(uint32_t*)&g_att[obA + d] = pack_h2(oc[nt][0] * iA, oc[nt][1] * iA);
        *(uint32_t*)&g_att[obB + d] = pack_h2(oc[nt][2] * iB, oc[nt][3] * iB);
    }
}

/* ========================================================================= */
extern "C" void kernel_launch(void* const* d_in, const int* in_sizes, int n_in,
                              void* d_out, int out_size)
{
    (void)in_sizes; (void)n_in; (void)out_size;
    const float* x      = (const float*)d_in[0];
    const float* theta  = (const float*)d_in[1];
    const float* qkv_w  = (const float*)d_in[2];
    const float* qkv_b  = (const float*)d_in[3];
    const float* proj_w = (const float*)d_in[4];
    const float* proj_b = (const float*)d_in[5];
    const float* a_p    = (const float*)d_in[6];
    const float* b_p    = (const float*)d_in[7];
    const float* a_r    = (const float*)d_in[8];
    const float* b_r    = (const float*)d_in[9];
    float* out = (float*)d_out;

    static int smem_set = 0;
    if (!smem_set) {
        cudaFuncSetAttribute(mma_gemm<0>, cudaFuncAttributeMaxDynamicSharedMemorySize, SMEM_TOTAL);
        cudaFuncSetAttribute(mma_gemm<1>, cudaFuncAttributeMaxDynamicSharedMemorySize, SMEM_TOTAL);
        smem_set = 1;
    }

    bias_kernel<<<256, 256>>>(theta, a_p, b_p, a_r, b_r);
    cvt_kernel<<<(M_TOT * DIMC / 4 + 255) / 256, 256>>>(x, 0, M_TOT * DIMC / 4);
    cvt_kernel<<<(3 * DIMC * DIMC / 4 + 255) / 256, 256>>>(qkv_w, 1, 3 * DIMC * DIMC / 4);
    cvt_kernel<<<(DIMC * DIMC / 4 + 255) / 256, 256>>>(proj_w, 2, DIMC * DIMC / 4);
    mma_gemm<0><<<dim3(12, 512), 256, SMEM_TOTAL>>>(qkv_b, nullptr);
    attn_mma_kernel<<<B_WIN * 8, 256>>>();
    mma_gemm<1><<<dim3(4, 512), 256, SMEM_TOTAL>>>(proj_b, out);
}